// round 6
// baseline (speedup 1.0000x reference)
#include <cuda_runtime.h>
#include <math.h>
#include <stdint.h>

// Problem dims (fixed by the reference)
#define B_ 8
#define T_ 2048
#define C_ 1024
#define F_ 4096
#define M_ (B_ * T_)   // 16384 rows

constexpr size_t S_  = (size_t)M_ * C_;   // 16,777,216
constexpr size_t SF_ = (size_t)M_ * F_;   // 67,108,864
constexpr size_t CC_ = (size_t)C_ * C_;
constexpr size_t FC_ = (size_t)F_ * C_;

#define NCH 16            // WKV chunks
#define CHL (T_ / NCH)    // 128 steps per chunk
#define NCHAN (B_ * C_)   // 8192 channels

// ---------------------------------------------------------------------------
// Scratch (static device globals — allocation-free per harness rules)
// ---------------------------------------------------------------------------
__device__ float g_h[S_];
__device__ float g_xk[S_];
__device__ float g_xv[S_];
__device__ float g_xr[S_];
__device__ float g_k[S_];
__device__ float g_v[S_];
__device__ float g_r[S_];
__device__ float g_rwkv[S_];
__device__ float g_short[S_];
__device__ float g_x2[S_];
__device__ float g_g[S_];
__device__ float g_gk[S_];
__device__ float g_gr[S_];
__device__ float g_kv[S_];
__device__ float g_kk[SF_];
__device__ float g_xt[S_];      // tf32-rounded copy of x
// tf32-rounded weights
__device__ float g_wkt[CC_];
__device__ float g_wvt[CC_];
__device__ float g_wrt[CC_];
__device__ float g_wot[CC_];
__device__ float g_wst[CC_];
__device__ float g_fwrt[CC_];
__device__ float g_fwkt[FC_];
__device__ float g_fwvt[FC_];
// WKV chunk-scan state
__device__ float g_sa[NCHAN * NCH], g_sbv[NCHAN * NCH], g_sp[NCHAN * NCH];
__device__ float g_pa[NCHAN * NCH], g_pbv[NCHAN * NCH], g_pp[NCHAN * NCH];

// ---------------------------------------------------------------------------
// helpers
// ---------------------------------------------------------------------------
__device__ __forceinline__ uint32_t f2tf32(float f) {
    uint32_t u;
    asm("cvt.rna.tf32.f32 %0, %1;" : "=r"(u) : "f"(f));
    return u;
}
__device__ __forceinline__ float f2tf32f(float f) {
    return __uint_as_float(f2tf32(f));
}

__device__ __forceinline__ void cp_async16(void* smem, const void* gmem) {
    uint32_t s = (uint32_t)__cvta_generic_to_shared(smem);
    asm volatile("cp.async.cg.shared.global [%0], [%1], 16;" :: "r"(s), "l"(gmem));
}
#define CP_COMMIT() asm volatile("cp.async.commit_group;")
#define CP_WAIT0()  asm volatile("cp.async.wait_group 0;")
#define CP_WAIT1()  asm volatile("cp.async.wait_group 1;")

__device__ __forceinline__ void mma_tf32(float* d, const uint32_t* a, const uint32_t* b) {
    asm volatile(
        "mma.sync.aligned.m16n8k8.row.col.f32.tf32.tf32.f32 "
        "{%0,%1,%2,%3}, {%4,%5,%6,%7}, {%8,%9}, {%0,%1,%2,%3};"
        : "+f"(d[0]), "+f"(d[1]), "+f"(d[2]), "+f"(d[3])
        : "r"(a[0]), "r"(a[1]), "r"(a[2]), "r"(a[3]),
          "r"(b[0]), "r"(b[1]));
}

// ---------------------------------------------------------------------------
// tf32 copy-convert (for x and all weights)
// ---------------------------------------------------------------------------
__global__ void __launch_bounds__(256) cvt_kernel(const float* __restrict__ src,
                                                  float* __restrict__ dst,
                                                  int n4) {
    int i = blockIdx.x * blockDim.x + threadIdx.x;
    if (i >= n4) return;
    float4 v = ((const float4*)src)[i];
    float4 o;
    o.x = f2tf32f(v.x); o.y = f2tf32f(v.y);
    o.z = f2tf32f(v.z); o.w = f2tf32f(v.w);
    ((float4*)dst)[i] = o;
}

// ---------------------------------------------------------------------------
// LayerNorm over last dim (C=1024). 256 thr per row, one float4 per thread.
// ---------------------------------------------------------------------------
__global__ void __launch_bounds__(256) ln_kernel(const float* __restrict__ x,
                                                 const float* __restrict__ w,
                                                 const float* __restrict__ b,
                                                 float* __restrict__ out) {
    const size_t row = blockIdx.x;
    const float4* xr = (const float4*)(x + row * C_);
    const int tid = threadIdx.x;

    float4 xv = xr[tid];
    float s  = xv.x + xv.y + xv.z + xv.w;
    float ss = xv.x * xv.x + xv.y * xv.y + xv.z * xv.z + xv.w * xv.w;

    #pragma unroll
    for (int o = 16; o > 0; o >>= 1) {
        s  += __shfl_down_sync(0xffffffffu, s,  o);
        ss += __shfl_down_sync(0xffffffffu, ss, o);
    }
    __shared__ float sm_s[8], sm_ss[8];
    int wid = tid >> 5, lid = tid & 31;
    if (lid == 0) { sm_s[wid] = s; sm_ss[wid] = ss; }
    __syncthreads();
    if (wid == 0) {
        s  = (lid < 8) ? sm_s[lid]  : 0.f;
        ss = (lid < 8) ? sm_ss[lid] : 0.f;
        #pragma unroll
        for (int o = 4; o > 0; o >>= 1) {
            s  += __shfl_down_sync(0xffffffffu, s,  o);
            ss += __shfl_down_sync(0xffffffffu, ss, o);
        }
        if (lid == 0) { sm_s[0] = s; sm_ss[0] = ss; }
    }
    __syncthreads();
    const float mean = sm_s[0] * (1.0f / C_);
    const float var  = sm_ss[0] * (1.0f / C_) - mean * mean;
    const float rstd = rsqrtf(var + 1e-5f);

    float4 wv = ((const float4*)w)[tid];
    float4 bv = ((const float4*)b)[tid];
    float4 ov;
    ov.x = (xv.x - mean) * rstd * wv.x + bv.x;
    ov.y = (xv.y - mean) * rstd * wv.y + bv.y;
    ov.z = (xv.z - mean) * rstd * wv.z + bv.z;
    ov.w = (xv.w - mean) * rstd * wv.w + bv.w;
    ((float4*)(out + row * C_))[tid] = ov;
}

// ---------------------------------------------------------------------------
// Time-shift + mix; outputs tf32-rounded (GEMM inputs)
// ---------------------------------------------------------------------------
__global__ void __launch_bounds__(256) mix3_kernel(const float* __restrict__ h,
                                                   const float* __restrict__ mk,
                                                   const float* __restrict__ mv,
                                                   const float* __restrict__ mr,
                                                   float* __restrict__ xk,
                                                   float* __restrict__ xv,
                                                   float* __restrict__ xr) {
    size_t idx = (size_t)blockIdx.x * blockDim.x + threadIdx.x;
    if (idx >= S_) return;
    const int c = (int)(idx & (C_ - 1));
    const size_t row = idx >> 10;
    const int t = (int)(row & (T_ - 1));
    float hc = h[idx];
    float hh = (t == 0) ? 0.f : h[idx - C_];
    float a;
    a = mk[c]; xk[idx] = f2tf32f(hc * a + hh * (1.f - a));
    a = mv[c]; xv[idx] = f2tf32f(hc * a + hh * (1.f - a));
    a = mr[c]; xr[idx] = f2tf32f(hc * a + hh * (1.f - a));
}

__global__ void __launch_bounds__(256) mix2_kernel(const float* __restrict__ h,
                                                   const float* __restrict__ mk,
                                                   const float* __restrict__ mr,
                                                   float* __restrict__ xk,
                                                   float* __restrict__ xr) {
    size_t idx = (size_t)blockIdx.x * blockDim.x + threadIdx.x;
    if (idx >= S_) return;
    const int c = (int)(idx & (C_ - 1));
    const size_t row = idx >> 10;
    const int t = (int)(row & (T_ - 1));
    float hc = h[idx];
    float hh = (t == 0) ? 0.f : h[idx - C_];
    float a;
    a = mk[c]; xk[idx] = f2tf32f(hc * a + hh * (1.f - a));
    a = mr[c]; xr[idx] = f2tf32f(hc * a + hh * (1.f - a));
}

// ---------------------------------------------------------------------------
// WKV chunk-parallel scan (3 passes).
// ---------------------------------------------------------------------------
__global__ void __launch_bounds__(256) wkv_part(const float* __restrict__ decay,
                                                const float* __restrict__ k,
                                                const float* __restrict__ v) {
    int gid = blockIdx.x * blockDim.x + threadIdx.x;  // 131072
    int j    = gid >> 13;          // chunk 0..15
    int chan = gid & (NCHAN - 1);  // 0..8191
    int b = chan >> 10;
    int c = chan & (C_ - 1);
    const float w = -__expf(decay[c]);
    size_t off = ((size_t)b * T_ + (size_t)j * CHL) * C_ + c;

    float a = 0.f, bb = 0.f, p = -1e30f;
    #pragma unroll 4
    for (int t = 0; t < CHL; ++t, off += C_) {
        const float kt = k[off];
        const float vt = v[off];
        const float ww2 = p + w;
        const float q2  = fmaxf(ww2, kt);
        const float f1  = __expf(ww2 - q2);
        const float f2  = __expf(kt - q2);
        a  = f1 * a + f2 * vt;
        bb = f1 * bb + f2;
        p  = q2;
    }
    g_sa[j * NCHAN + chan]  = a;
    g_sbv[j * NCHAN + chan] = bb;
    g_sp[j * NCHAN + chan]  = p;
}

__global__ void __launch_bounds__(256) wkv_scan(const float* __restrict__ decay) {
    int chan = blockIdx.x * blockDim.x + threadIdx.x;  // 8192
    if (chan >= NCHAN) return;
    int c = chan & (C_ - 1);
    const float w = -__expf(decay[c]);
    const float Lw = (float)CHL * w;

    float a = 0.f, bb = 0.f, p = -1e30f;
    #pragma unroll
    for (int j = 0; j < NCH; ++j) {
        g_pa[j * NCHAN + chan]  = a;
        g_pbv[j * NCHAN + chan] = bb;
        g_pp[j * NCHAN + chan]  = p;
        const float ca = g_sa[j * NCHAN + chan];
        const float cb = g_sbv[j * NCHAN + chan];
        const float cp = g_sp[j * NCHAN + chan];
        const float pw = p + Lw;
        const float q  = fmaxf(pw, cp);
        const float e0 = __expf(pw - q);
        const float e1 = __expf(cp - q);
        a  = a * e0 + ca * e1;
        bb = bb * e0 + cb * e1;
        p  = q;
    }
}

__global__ void __launch_bounds__(256) wkv_out(const float* __restrict__ decay,
                                               const float* __restrict__ first,
                                               const float* __restrict__ k,
                                               const float* __restrict__ v,
                                               const float* __restrict__ r,
                                               float* __restrict__ out) {
    int gid = blockIdx.x * blockDim.x + threadIdx.x;
    int j    = gid >> 13;
    int chan = gid & (NCHAN - 1);
    int b = chan >> 10;
    int c = chan & (C_ - 1);
    const float w = -__expf(decay[c]);
    const float u = first[c];
    size_t off = ((size_t)b * T_ + (size_t)j * CHL) * C_ + c;

    float a  = g_pa[j * NCHAN + chan];
    float bb = g_pbv[j * NCHAN + chan];
    float p  = g_pp[j * NCHAN + chan];

    #pragma unroll 4
    for (int t = 0; t < CHL; ++t, off += C_) {
        const float kt = k[off];
        const float vt = v[off];
        const float ww = u + kt;
        const float q  = fmaxf(p, ww);
        const float e1 = __expf(p - q);
        const float e2 = __expf(ww - q);
        const float y  = (e1 * a + e2 * vt) / (e1 * bb + e2);
        out[off] = f2tf32f(y * r[off]);
        const float ww2 = p + w;
        const float q2  = fmaxf(ww2, kt);
        const float f1  = __expf(ww2 - q2);
        const float f2  = __expf(kt - q2);
        a  = f1 * a + f2 * vt;
        bb = f1 * bb + f2;
        p  = q2;
    }
}

// ---------------------------------------------------------------------------
// tf32 tensor-core GEMM:  C[M,N] = A[M,K] * W[N,K]^T
// 128x128 CTA tile, BK=16, 128 threads = 4 warps @ 64x64 warp tiles,
// 3-stage cp.async pipeline, 2 CTAs/SM.
// MODE: 0 = store, 1 = sigmoid, 2 = relu^2 (+tf32 round), 3 = +aux1,
//       4 = aux1 + sigmoid(acc)*aux2
// ---------------------------------------------------------------------------
#define BM 128
#define BN 128
#define BK 16
#define BKP 20   // padded k-stride (floats): conflict-free frag loads, 16B aligned
#define STG 3
#define STAGE_FLTS (128 * BKP)
#define GEMM_SMEM (STG * STAGE_FLTS * 2 * 4)   // 61440 bytes

template <int MODE>
__global__ void __launch_bounds__(128, 2) gemm_tc(const float* __restrict__ A,
                                                  const float* __restrict__ W,
                                                  float* __restrict__ Cc,
                                                  const float* __restrict__ aux1,
                                                  const float* __restrict__ aux2,
                                                  int N, int K) {
    extern __shared__ float sm[];
    float* AsBase = sm;                      // [STG][128][BKP]
    float* BsBase = sm + STG * STAGE_FLTS;   // [STG][128][BKP]

    const int tid  = threadIdx.x;
    const int wid  = tid >> 5;
    const int lane = tid & 31;
    const int g    = lane >> 2;   // 0..7
    const int tig  = lane & 3;    // 0..3

    const int warp_m = wid >> 1;  // 0..1 -> 64 rows
    const int warp_n = wid & 1;   // 0..1 -> 64 cols

    const size_t brow = blockIdx.y;
    const size_t bcol = blockIdx.x;

    // loader: thread handles full BK=16 of one row (4 x 16B chunks)
    const float* Ag = A + (brow * BM + tid) * (size_t)K;
    const float* Wg = W + (bcol * BN + tid) * (size_t)K;

    float acc[4][8][4];
    #pragma unroll
    for (int i = 0; i < 4; ++i)
        #pragma unroll
        for (int j = 0; j < 8; ++j)
            #pragma unroll
            for (int r = 0; r < 4; ++r) acc[i][j][r] = 0.f;

    auto load_stage = [&](int s, int k0) {
        float* a = AsBase + s * STAGE_FLTS + tid * BKP;
        float* b = BsBase + s * STAGE_FLTS + tid * BKP;
        #pragma unroll
        for (int q = 0; q < 4; ++q) {
            cp_async16(a + q * 4, Ag + k0 + q * 4);
            cp_async16(b + q * 4, Wg + k0 + q * 4);
        }
    };

    load_stage(0, 0); CP_COMMIT();
    load_stage(1, BK); CP_COMMIT();

    const int nk = K / BK;
    for (int it = 0; it < nk; ++it) {
        const int cur = it % 3;
        if (it == nk - 1) { CP_WAIT0(); } else { CP_WAIT1(); }
        __syncthreads();

        const uint32_t* As = (const uint32_t*)(AsBase + cur * STAGE_FLTS);
        const uint32_t* Bs = (const uint32_t*)(BsBase + cur * STAGE_FLTS);

        #pragma unroll
        for (int ks = 0; ks < 2; ++ks) {
            const int kb = ks * 8;
            uint32_t af[4][4];
            uint32_t bf[8][2];
            #pragma unroll
            for (int mt = 0; mt < 4; ++mt) {
                const int row = warp_m * 64 + mt * 16;
                af[mt][0] = As[(row + g    ) * BKP + kb + tig];
                af[mt][1] = As[(row + g + 8) * BKP + kb + tig];
                af[mt][2] = As[(row + g    ) * BKP + kb + tig + 4];
                af[mt][3] = As[(row + g + 8) * BKP + kb + tig + 4];
            }
            #pragma unroll
            for (int nt = 0; nt < 8; ++nt) {
                const int col = warp_n * 64 + nt * 8;
                bf[nt][0] = Bs[(col + g) * BKP + kb + tig];
                bf[nt][1] = Bs[(col + g) * BKP + kb + tig + 4];
            }
            #pragma unroll
            for (int mt = 0; mt < 4; ++mt)
                #pragma unroll
                for (int nt = 0; nt < 8; ++nt)
                    mma_tf32(acc[mt][nt], af[mt], bf[nt]);
        }

        if (it + 2 < nk) {
            load_stage((it + 2) % 3, (it + 2) * BK);
            CP_COMMIT();
        }
    }

    // Epilogue
    #pragma unroll
    for (int mt = 0; mt < 4; ++mt) {
        const int r0 = (int)(brow * BM) + warp_m * 64 + mt * 16 + g;
        #pragma unroll
        for (int nt = 0; nt < 8; ++nt) {
            const int c0 = (int)(bcol * BN) + warp_n * 64 + nt * 8 + 2 * tig;
            #pragma unroll
            for (int half = 0; half < 2; ++half) {
                const int row = r0 + half * 8;
                const size_t off = (size_t)row * N + c0;
                float v0 = acc[mt][nt][half * 2 + 0];
                float v1 = acc[mt][nt][half * 2 + 1];
                if (MODE == 1) {
                    v0 = 1.f / (1.f + __expf(-v0));
                    v1 = 1.f / (1.f + __expf(-v1));
                } else if (MODE == 2) {
                    v0 = fmaxf(v0, 0.f); v0 = f2tf32f(v0 * v0);
                    v1 = fmaxf(v1, 0.f); v1 = f2tf32f(v1 * v1);
                } else if (MODE == 3) {
                    float2 a1 = *(const float2*)(aux1 + off);
                    v0 += a1.x; v1 += a1.y;
                } else if (MODE == 4) {
                    float2 a1 = *(const float2*)(aux1 + off);
                    float2 a2 = *(const float2*)(aux2 + off);
                    v0 = a1.x + (1.f / (1.f + __expf(-v0))) * a2.x;
                    v1 = a1.y + (1.f / (1.f + __expf(-v1))) * a2.y;
                }
                float2 o; o.x = v0; o.y = v1;
                *(float2*)(Cc + off) = o;
            }
        }
    }
}

// ---------------------------------------------------------------------------
// Launch
// ---------------------------------------------------------------------------
static float* sym(const void* s) {
    void* p = nullptr;
    cudaGetSymbolAddress(&p, s);
    return (float*)p;
}

extern "C" void kernel_launch(void* const* d_in, const int* in_sizes, int n_in,
                              void* d_out, int out_size) {
    const float* x        = (const float*)d_in[0];
    const float* ln1_w    = (const float*)d_in[1];
    const float* ln1_b    = (const float*)d_in[2];
    const float* ln2_w    = (const float*)d_in[3];
    const float* ln2_b    = (const float*)d_in[4];
    const float* t_decay  = (const float*)d_in[5];
    const float* t_first  = (const float*)d_in[6];
    const float* mix_k    = (const float*)d_in[7];
    const float* mix_v    = (const float*)d_in[8];
    const float* mix_r    = (const float*)d_in[9];
    const float* Wk       = (const float*)d_in[10];
    const float* Wv       = (const float*)d_in[11];
    const float* Wr       = (const float*)d_in[12];
    const float* Wo       = (const float*)d_in[13];
    const float* fmix_k   = (const float*)d_in[14];
    const float* fmix_r   = (const float*)d_in[15];
    const float* fWk      = (const float*)d_in[16];   // [F, C]
    const float* fWr      = (const float*)d_in[17];   // [C, C]
    const float* fWv      = (const float*)d_in[18];   // [C, F]
    const float* shortW   = (const float*)d_in[19];
    float* out = (float*)d_out;

    float* h    = sym(g_h);
    float* xk   = sym(g_xk);
    float* xv   = sym(g_xv);
    float* xr   = sym(g_xr);
    float* kbuf = sym(g_k);
    float* vbuf = sym(g_v);
    float* rbuf = sym(g_r);
    float* rwkv = sym(g_rwkv);
    float* shrt = sym(g_short);
    float* x2   = sym(g_x2);
    float* gbuf = sym(g_g);
    float* gk   = sym(g_gk);
    float* gr   = sym(g_gr);
    float* kvb  = sym(g_kv);
    float* kkb  = sym(g_kk);
    float* xt   = sym(g_xt);
    float* wkt  = sym(g_wkt);
    float* wvt  = sym(g_wvt);
    float* wrt  = sym(g_wrt);
    float* wot  = sym(g_wot);
    float* wst  = sym(g_wst);
    float* fwrt = sym(g_fwrt);
    float* fwkt = sym(g_fwkt);
    float* fwvt = sym(g_fwvt);

    cudaFuncSetAttribute(gemm_tc<0>, cudaFuncAttributeMaxDynamicSharedMemorySize, GEMM_SMEM);
    cudaFuncSetAttribute(gemm_tc<1>, cudaFuncAttributeMaxDynamicSharedMemorySize, GEMM_SMEM);
    cudaFuncSetAttribute(gemm_tc<2>, cudaFuncAttributeMaxDynamicSharedMemorySize, GEMM_SMEM);
    cudaFuncSetAttribute(gemm_tc<3>, cudaFuncAttributeMaxDynamicSharedMemorySize, GEMM_SMEM);
    cudaFuncSetAttribute(gemm_tc<4>, cudaFuncAttributeMaxDynamicSharedMemorySize, GEMM_SMEM);

    const dim3 blk(256);
    const dim3 gblk(128);
    const dim3 grid_elem((unsigned)((S_ + 255) / 256));
    const dim3 grid_gC(C_ / BN, M_ / BM);   // (8, 128)
    const dim3 grid_gF(F_ / BN, M_ / BM);   // (32, 128)

    // --- tf32 pre-conversion (weights + x) ---
    const int nCC4 = (int)(CC_ / 4), nFC4 = (int)(FC_ / 4), nS4 = (int)(S_ / 4);
    cvt_kernel<<<(nS4 + 255) / 256, blk>>>(x, xt, nS4);
    cvt_kernel<<<(nCC4 + 255) / 256, blk>>>(Wk, wkt, nCC4);
    cvt_kernel<<<(nCC4 + 255) / 256, blk>>>(Wv, wvt, nCC4);
    cvt_kernel<<<(nCC4 + 255) / 256, blk>>>(Wr, wrt, nCC4);
    cvt_kernel<<<(nCC4 + 255) / 256, blk>>>(Wo, wot, nCC4);
    cvt_kernel<<<(nCC4 + 255) / 256, blk>>>(shortW, wst, nCC4);
    cvt_kernel<<<(nCC4 + 255) / 256, blk>>>(fWr, fwrt, nCC4);
    cvt_kernel<<<(nFC4 + 255) / 256, blk>>>(fWk, fwkt, nFC4);
    cvt_kernel<<<(nFC4 + 255) / 256, blk>>>(fWv, fwvt, nFC4);

    // --- TimeMix path ---
    ln_kernel<<<M_, blk>>>(x, ln1_w, ln1_b, h);
    mix3_kernel<<<grid_elem, blk>>>(h, mix_k, mix_v, mix_r, xk, xv, xr);
    gemm_tc<0><<<grid_gC, gblk, GEMM_SMEM>>>(xk, wkt, kbuf, nullptr, nullptr, C_, C_);
    gemm_tc<0><<<grid_gC, gblk, GEMM_SMEM>>>(xv, wvt, vbuf, nullptr, nullptr, C_, C_);
    gemm_tc<1><<<grid_gC, gblk, GEMM_SMEM>>>(xr, wrt, rbuf, nullptr, nullptr, C_, C_);
    wkv_part<<<(NCHAN * NCH) / 256, blk>>>(t_decay, kbuf, vbuf);
    wkv_scan<<<NCHAN / 256, blk>>>(t_decay);
    wkv_out<<<(NCHAN * NCH) / 256, blk>>>(t_decay, t_first, kbuf, vbuf, rbuf, rwkv);
    gemm_tc<0><<<grid_gC, gblk, GEMM_SMEM>>>(xt, wst, shrt, nullptr, nullptr, C_, C_);
    gemm_tc<3><<<grid_gC, gblk, GEMM_SMEM>>>(rwkv, wot, x2, shrt, nullptr, C_, C_);

    // --- ChannelMix path ---
    ln_kernel<<<M_, blk>>>(x2, ln2_w, ln2_b, gbuf);
    mix2_kernel<<<grid_elem, blk>>>(gbuf, fmix_k, fmix_r, gk, gr);
    gemm_tc<2><<<grid_gF, gblk, GEMM_SMEM>>>(gk, fwkt, kkb, nullptr, nullptr, F_, C_);
    gemm_tc<0><<<grid_gC, gblk, GEMM_SMEM>>>(kkb, fwvt, kvb, nullptr, nullptr, C_, F_);
    gemm_tc<4><<<grid_gC, gblk, GEMM_SMEM>>>(gr, fwrt, out, x2, kvb, C_, C_);
}

// round 7
// speedup vs baseline: 2.2338x; 2.2338x over previous
#include <cuda_runtime.h>
#include <cuda_fp16.h>
#include <math.h>
#include <stdint.h>

// Problem dims (fixed by the reference)
#define B_ 8
#define T_ 2048
#define C_ 1024
#define F_ 4096
#define M_ (B_ * T_)   // 16384 rows

constexpr size_t S_  = (size_t)M_ * C_;   // 16,777,216
constexpr size_t SF_ = (size_t)M_ * F_;   // 67,108,864
constexpr size_t CC_ = (size_t)C_ * C_;
constexpr size_t FC_ = (size_t)F_ * C_;

#define NCH 16            // WKV chunks
#define CHL (T_ / NCH)    // 128 steps per chunk
#define NCHAN (B_ * C_)   // 8192 channels

// ---------------------------------------------------------------------------
// Scratch (static device globals — allocation-free per harness rules)
// ---------------------------------------------------------------------------
__device__ float  g_h[S_];
__device__ __half g_xk[S_];
__device__ __half g_xv[S_];
__device__ __half g_xr[S_];
__device__ float  g_k[S_];      // wkv inputs stay fp32
__device__ float  g_v[S_];
__device__ float  g_r[S_];
__device__ __half g_rwkv[S_];   // GEMM input -> half
__device__ float  g_short[S_];
__device__ float  g_x2[S_];
__device__ float  g_g[S_];
__device__ __half g_gk[S_];
__device__ __half g_gr[S_];
__device__ float  g_kv[S_];
__device__ __half g_kk[SF_];    // GEMM input -> half
__device__ __half g_xt[S_];     // half copy of x
// half weights
__device__ __half g_wkt[CC_];
__device__ __half g_wvt[CC_];
__device__ __half g_wrt[CC_];
__device__ __half g_wot[CC_];
__device__ __half g_wst[CC_];
__device__ __half g_fwrt[CC_];
__device__ __half g_fwkt[FC_];
__device__ __half g_fwvt[FC_];
// WKV chunk-scan state
__device__ float g_sa[NCHAN * NCH], g_sbv[NCHAN * NCH], g_sp[NCHAN * NCH];
__device__ float g_pa[NCHAN * NCH], g_pbv[NCHAN * NCH], g_pp[NCHAN * NCH];

// ---------------------------------------------------------------------------
// helpers
// ---------------------------------------------------------------------------
__device__ __forceinline__ void cp_async16(void* smem, const void* gmem) {
    uint32_t s = (uint32_t)__cvta_generic_to_shared(smem);
    asm volatile("cp.async.cg.shared.global [%0], [%1], 16;" :: "r"(s), "l"(gmem));
}
#define CP_COMMIT() asm volatile("cp.async.commit_group;")
#define CP_WAIT0()  asm volatile("cp.async.wait_group 0;")
#define CP_WAIT1()  asm volatile("cp.async.wait_group 1;")

// fp16 mma with fp32 accumulate: D(16x8) += A(16x16) * B(16x8)
__device__ __forceinline__ void mma_f16(float* d, const uint32_t* a, const uint32_t* b) {
    asm volatile(
        "mma.sync.aligned.m16n8k16.row.col.f32.f16.f16.f32 "
        "{%0,%1,%2,%3}, {%4,%5,%6,%7}, {%8,%9}, {%0,%1,%2,%3};"
        : "+f"(d[0]), "+f"(d[1]), "+f"(d[2]), "+f"(d[3])
        : "r"(a[0]), "r"(a[1]), "r"(a[2]), "r"(a[3]),
          "r"(b[0]), "r"(b[1]));
}

// ---------------------------------------------------------------------------
// float -> half copy-convert (weights + x)
// ---------------------------------------------------------------------------
__global__ void __launch_bounds__(256) cvt_kernel(const float* __restrict__ src,
                                                  __half* __restrict__ dst,
                                                  int n4) {
    int i = blockIdx.x * blockDim.x + threadIdx.x;
    if (i >= n4) return;
    float4 v = ((const float4*)src)[i];
    __half2 h0 = __floats2half2_rn(v.x, v.y);
    __half2 h1 = __floats2half2_rn(v.z, v.w);
    uint2 o;
    o.x = *(uint32_t*)&h0;
    o.y = *(uint32_t*)&h1;
    ((uint2*)dst)[i] = o;
}

// ---------------------------------------------------------------------------
// LayerNorm over last dim (C=1024). 256 thr per row, one float4 per thread.
// ---------------------------------------------------------------------------
__global__ void __launch_bounds__(256) ln_kernel(const float* __restrict__ x,
                                                 const float* __restrict__ w,
                                                 const float* __restrict__ b,
                                                 float* __restrict__ out) {
    const size_t row = blockIdx.x;
    const float4* xr = (const float4*)(x + row * C_);
    const int tid = threadIdx.x;

    float4 xv = xr[tid];
    float s  = xv.x + xv.y + xv.z + xv.w;
    float ss = xv.x * xv.x + xv.y * xv.y + xv.z * xv.z + xv.w * xv.w;

    #pragma unroll
    for (int o = 16; o > 0; o >>= 1) {
        s  += __shfl_down_sync(0xffffffffu, s,  o);
        ss += __shfl_down_sync(0xffffffffu, ss, o);
    }
    __shared__ float sm_s[8], sm_ss[8];
    int wid = tid >> 5, lid = tid & 31;
    if (lid == 0) { sm_s[wid] = s; sm_ss[wid] = ss; }
    __syncthreads();
    if (wid == 0) {
        s  = (lid < 8) ? sm_s[lid]  : 0.f;
        ss = (lid < 8) ? sm_ss[lid] : 0.f;
        #pragma unroll
        for (int o = 4; o > 0; o >>= 1) {
            s  += __shfl_down_sync(0xffffffffu, s,  o);
            ss += __shfl_down_sync(0xffffffffu, ss, o);
        }
        if (lid == 0) { sm_s[0] = s; sm_ss[0] = ss; }
    }
    __syncthreads();
    const float mean = sm_s[0] * (1.0f / C_);
    const float var  = sm_ss[0] * (1.0f / C_) - mean * mean;
    const float rstd = rsqrtf(var + 1e-5f);

    float4 wv = ((const float4*)w)[tid];
    float4 bv = ((const float4*)b)[tid];
    float4 ov;
    ov.x = (xv.x - mean) * rstd * wv.x + bv.x;
    ov.y = (xv.y - mean) * rstd * wv.y + bv.y;
    ov.z = (xv.z - mean) * rstd * wv.z + bv.z;
    ov.w = (xv.w - mean) * rstd * wv.w + bv.w;
    ((float4*)(out + row * C_))[tid] = ov;
}

// ---------------------------------------------------------------------------
// Time-shift + mix; outputs half (GEMM inputs)
// ---------------------------------------------------------------------------
__global__ void __launch_bounds__(256) mix3_kernel(const float* __restrict__ h,
                                                   const float* __restrict__ mk,
                                                   const float* __restrict__ mv,
                                                   const float* __restrict__ mr,
                                                   __half* __restrict__ xk,
                                                   __half* __restrict__ xv,
                                                   __half* __restrict__ xr) {
    size_t idx = (size_t)blockIdx.x * blockDim.x + threadIdx.x;
    if (idx >= S_) return;
    const int c = (int)(idx & (C_ - 1));
    const size_t row = idx >> 10;
    const int t = (int)(row & (T_ - 1));
    float hc = h[idx];
    float hh = (t == 0) ? 0.f : h[idx - C_];
    float a;
    a = mk[c]; xk[idx] = __float2half_rn(hc * a + hh * (1.f - a));
    a = mv[c]; xv[idx] = __float2half_rn(hc * a + hh * (1.f - a));
    a = mr[c]; xr[idx] = __float2half_rn(hc * a + hh * (1.f - a));
}

__global__ void __launch_bounds__(256) mix2_kernel(const float* __restrict__ h,
                                                   const float* __restrict__ mk,
                                                   const float* __restrict__ mr,
                                                   __half* __restrict__ xk,
                                                   __half* __restrict__ xr) {
    size_t idx = (size_t)blockIdx.x * blockDim.x + threadIdx.x;
    if (idx >= S_) return;
    const int c = (int)(idx & (C_ - 1));
    const size_t row = idx >> 10;
    const int t = (int)(row & (T_ - 1));
    float hc = h[idx];
    float hh = (t == 0) ? 0.f : h[idx - C_];
    float a;
    a = mk[c]; xk[idx] = __float2half_rn(hc * a + hh * (1.f - a));
    a = mr[c]; xr[idx] = __float2half_rn(hc * a + hh * (1.f - a));
}

// ---------------------------------------------------------------------------
// WKV chunk-parallel scan (3 passes). fp32 in, half out (feeds Wo GEMM).
// ---------------------------------------------------------------------------
__global__ void __launch_bounds__(256) wkv_part(const float* __restrict__ decay,
                                                const float* __restrict__ k,
                                                const float* __restrict__ v) {
    int gid = blockIdx.x * blockDim.x + threadIdx.x;  // 131072
    int j    = gid >> 13;          // chunk 0..15
    int chan = gid & (NCHAN - 1);  // 0..8191
    int b = chan >> 10;
    int c = chan & (C_ - 1);
    const float w = -__expf(decay[c]);
    size_t off = ((size_t)b * T_ + (size_t)j * CHL) * C_ + c;

    float a = 0.f, bb = 0.f, p = -1e30f;
    #pragma unroll 4
    for (int t = 0; t < CHL; ++t, off += C_) {
        const float kt = k[off];
        const float vt = v[off];
        const float ww2 = p + w;
        const float q2  = fmaxf(ww2, kt);
        const float f1  = __expf(ww2 - q2);
        const float f2  = __expf(kt - q2);
        a  = f1 * a + f2 * vt;
        bb = f1 * bb + f2;
        p  = q2;
    }
    g_sa[j * NCHAN + chan]  = a;
    g_sbv[j * NCHAN + chan] = bb;
    g_sp[j * NCHAN + chan]  = p;
}

__global__ void __launch_bounds__(256) wkv_scan(const float* __restrict__ decay) {
    int chan = blockIdx.x * blockDim.x + threadIdx.x;  // 8192
    if (chan >= NCHAN) return;
    int c = chan & (C_ - 1);
    const float w = -__expf(decay[c]);
    const float Lw = (float)CHL * w;

    float a = 0.f, bb = 0.f, p = -1e30f;
    #pragma unroll
    for (int j = 0; j < NCH; ++j) {
        g_pa[j * NCHAN + chan]  = a;
        g_pbv[j * NCHAN + chan] = bb;
        g_pp[j * NCHAN + chan]  = p;
        const float ca = g_sa[j * NCHAN + chan];
        const float cb = g_sbv[j * NCHAN + chan];
        const float cp = g_sp[j * NCHAN + chan];
        const float pw = p + Lw;
        const float q  = fmaxf(pw, cp);
        const float e0 = __expf(pw - q);
        const float e1 = __expf(cp - q);
        a  = a * e0 + ca * e1;
        bb = bb * e0 + cb * e1;
        p  = q;
    }
}

__global__ void __launch_bounds__(256) wkv_out(const float* __restrict__ decay,
                                               const float* __restrict__ first,
                                               const float* __restrict__ k,
                                               const float* __restrict__ v,
                                               const float* __restrict__ r,
                                               __half* __restrict__ out) {
    int gid = blockIdx.x * blockDim.x + threadIdx.x;
    int j    = gid >> 13;
    int chan = gid & (NCHAN - 1);
    int b = chan >> 10;
    int c = chan & (C_ - 1);
    const float w = -__expf(decay[c]);
    const float u = first[c];
    size_t off = ((size_t)b * T_ + (size_t)j * CHL) * C_ + c;

    float a  = g_pa[j * NCHAN + chan];
    float bb = g_pbv[j * NCHAN + chan];
    float p  = g_pp[j * NCHAN + chan];

    #pragma unroll 4
    for (int t = 0; t < CHL; ++t, off += C_) {
        const float kt = k[off];
        const float vt = v[off];
        const float ww = u + kt;
        const float q  = fmaxf(p, ww);
        const float e1 = __expf(p - q);
        const float e2 = __expf(ww - q);
        const float y  = (e1 * a + e2 * vt) / (e1 * bb + e2);
        out[off] = __float2half_rn(y * r[off]);
        const float ww2 = p + w;
        const float q2  = fmaxf(ww2, kt);
        const float f1  = __expf(ww2 - q2);
        const float f2  = __expf(kt - q2);
        a  = f1 * a + f2 * vt;
        bb = f1 * bb + f2;
        p  = q2;
    }
}

// ---------------------------------------------------------------------------
// fp16 tensor-core GEMM:  C[M,N] = A[M,K] * W[N,K]^T   (A, W half; C fp32 acc)
// 128x128 CTA tile, BK=32 (halfs), 256 threads (8 warps @ 64x32),
// 3-stage cp.async pipeline, 2 CTAs/SM.
// MODE: 0 = store f32, 1 = sigmoid f32, 2 = relu^2 -> half, 3 = +aux1 f32,
//       4 = aux1 + sigmoid(acc)*aux2 f32
// ---------------------------------------------------------------------------
#define BM 128
#define BN 128
#define BK 32            // halfs per stage in K
#define BKPH 40          // padded halfs per row (=20 words, conflict-free)
#define STG 3
#define STAGE_HALFS (128 * BKPH)
#define GEMM_SMEM (STG * STAGE_HALFS * 2 * 2)   // 61440 bytes

template <int MODE>
__global__ void __launch_bounds__(256, 2) gemm_tc(const __half* __restrict__ A,
                                                  const __half* __restrict__ W,
                                                  void* __restrict__ Cc,
                                                  const float* __restrict__ aux1,
                                                  const float* __restrict__ aux2,
                                                  int N, int K) {
    extern __shared__ __half smh[];
    __half* AsBase = smh;                       // [STG][128][BKPH]
    __half* BsBase = smh + STG * STAGE_HALFS;   // [STG][128][BKPH]

    const int tid  = threadIdx.x;
    const int wid  = tid >> 5;
    const int lane = tid & 31;
    const int g    = lane >> 2;   // 0..7
    const int tig  = lane & 3;    // 0..3

    const int warp_m = wid >> 2;  // 0..1 -> 64 rows
    const int warp_n = wid & 3;   // 0..3 -> 32 cols

    const size_t brow = blockIdx.y;
    const size_t bcol = blockIdx.x;

    // loader: 2 threads per row; each loads 2 x 16B (16 halfs)
    const int lrow = tid >> 1;           // 0..127
    const int lk   = (tid & 1) * 16;     // 0 or 16 (halfs)

    const __half* Ag = A + (brow * BM + lrow) * (size_t)K + lk;
    const __half* Wg = W + (bcol * BN + lrow) * (size_t)K + lk;

    float acc[4][4][4];
    #pragma unroll
    for (int i = 0; i < 4; ++i)
        #pragma unroll
        for (int j = 0; j < 4; ++j)
            #pragma unroll
            for (int r = 0; r < 4; ++r) acc[i][j][r] = 0.f;

    auto load_stage = [&](int s, int k0) {
        __half* a = AsBase + s * STAGE_HALFS + lrow * BKPH + lk;
        __half* b = BsBase + s * STAGE_HALFS + lrow * BKPH + lk;
        cp_async16(a,     Ag + k0);
        cp_async16(a + 8, Ag + k0 + 8);
        cp_async16(b,     Wg + k0);
        cp_async16(b + 8, Wg + k0 + 8);
    };

    load_stage(0, 0); CP_COMMIT();
    load_stage(1, BK); CP_COMMIT();

    const int nk = K / BK;
    for (int it = 0; it < nk; ++it) {
        const int cur = it % 3;
        if (it == nk - 1) { CP_WAIT0(); } else { CP_WAIT1(); }
        __syncthreads();

        const uint32_t* As = (const uint32_t*)(AsBase + cur * STAGE_HALFS);
        const uint32_t* Bs = (const uint32_t*)(BsBase + cur * STAGE_HALFS);

        #pragma unroll
        for (int ks = 0; ks < 2; ++ks) {
            const int kw = ks * 8;   // word offset within row (16 halfs per kstep)
            uint32_t af[4][4];
            uint32_t bf[4][2];
            #pragma unroll
            for (int mt = 0; mt < 4; ++mt) {
                const int row = warp_m * 64 + mt * 16;
                af[mt][0] = As[(row + g    ) * (BKPH / 2) + kw + tig];
                af[mt][1] = As[(row + g + 8) * (BKPH / 2) + kw + tig];
                af[mt][2] = As[(row + g    ) * (BKPH / 2) + kw + 4 + tig];
                af[mt][3] = As[(row + g + 8) * (BKPH / 2) + kw + 4 + tig];
            }
            #pragma unroll
            for (int nt = 0; nt < 4; ++nt) {
                const int col = warp_n * 32 + nt * 8;
                bf[nt][0] = Bs[(col + g) * (BKPH / 2) + kw + tig];
                bf[nt][1] = Bs[(col + g) * (BKPH / 2) + kw + 4 + tig];
            }
            #pragma unroll
            for (int mt = 0; mt < 4; ++mt)
                #pragma unroll
                for (int nt = 0; nt < 4; ++nt)
                    mma_f16(acc[mt][nt], af[mt], bf[nt]);
        }

        if (it + 2 < nk) {
            load_stage((it + 2) % 3, (it + 2) * BK);
            CP_COMMIT();
        }
    }

    // Epilogue
    #pragma unroll
    for (int mt = 0; mt < 4; ++mt) {
        const int r0 = (int)(brow * BM) + warp_m * 64 + mt * 16 + g;
        #pragma unroll
        for (int nt = 0; nt < 4; ++nt) {
            const int c0 = (int)(bcol * BN) + warp_n * 32 + nt * 8 + 2 * tig;
            #pragma unroll
            for (int half_i = 0; half_i < 2; ++half_i) {
                const int row = r0 + half_i * 8;
                const size_t off = (size_t)row * N + c0;
                float v0 = acc[mt][nt][half_i * 2 + 0];
                float v1 = acc[mt][nt][half_i * 2 + 1];
                if (MODE == 1) {
                    v0 = 1.f / (1.f + __expf(-v0));
                    v1 = 1.f / (1.f + __expf(-v1));
                } else if (MODE == 2) {
                    v0 = fmaxf(v0, 0.f); v0 = v0 * v0;
                    v1 = fmaxf(v1, 0.f); v1 = v1 * v1;
                } else if (MODE == 3) {
                    float2 a1 = *(const float2*)(aux1 + off);
                    v0 += a1.x; v1 += a1.y;
                } else if (MODE == 4) {
                    float2 a1 = *(const float2*)(aux1 + off);
                    float2 a2 = *(const float2*)(aux2 + off);
                    v0 = a1.x + (1.f / (1.f + __expf(-v0))) * a2.x;
                    v1 = a1.y + (1.f / (1.f + __expf(-v1))) * a2.y;
                }
                if (MODE == 2) {
                    __half2 hv = __floats2half2_rn(v0, v1);
                    *(__half2*)((__half*)Cc + off) = hv;
                } else {
                    float2 o; o.x = v0; o.y = v1;
                    *(float2*)((float*)Cc + off) = o;
                }
            }
        }
    }
}

// ---------------------------------------------------------------------------
// Launch
// ---------------------------------------------------------------------------
template <typename T>
static T* sym(const void* s) {
    void* p = nullptr;
    cudaGetSymbolAddress(&p, s);
    return (T*)p;
}

extern "C" void kernel_launch(void* const* d_in, const int* in_sizes, int n_in,
                              void* d_out, int out_size) {
    const float* x        = (const float*)d_in[0];
    const float* ln1_w    = (const float*)d_in[1];
    const float* ln1_b    = (const float*)d_in[2];
    const float* ln2_w    = (const float*)d_in[3];
    const float* ln2_b    = (const float*)d_in[4];
    const float* t_decay  = (const float*)d_in[5];
    const float* t_first  = (const float*)d_in[6];
    const float* mix_k    = (const float*)d_in[7];
    const float* mix_v    = (const float*)d_in[8];
    const float* mix_r    = (const float*)d_in[9];
    const float* Wk       = (const float*)d_in[10];
    const float* Wv       = (const float*)d_in[11];
    const float* Wr       = (const float*)d_in[12];
    const float* Wo       = (const float*)d_in[13];
    const float* fmix_k   = (const float*)d_in[14];
    const float* fmix_r   = (const float*)d_in[15];
    const float* fWk      = (const float*)d_in[16];   // [F, C]
    const float* fWr      = (const float*)d_in[17];   // [C, C]
    const float* fWv      = (const float*)d_in[18];   // [C, F]
    const float* shortW   = (const float*)d_in[19];
    float* out = (float*)d_out;

    float*  h    = sym<float>(g_h);
    __half* xk   = sym<__half>(g_xk);
    __half* xv   = sym<__half>(g_xv);
    __half* xr   = sym<__half>(g_xr);
    float*  kbuf = sym<float>(g_k);
    float*  vbuf = sym<float>(g_v);
    float*  rbuf = sym<float>(g_r);
    __half* rwkv = sym<__half>(g_rwkv);
    float*  shrt = sym<float>(g_short);
    float*  x2   = sym<float>(g_x2);
    float*  gbuf = sym<float>(g_g);
    __half* gk   = sym<__half>(g_gk);
    __half* gr   = sym<__half>(g_gr);
    float*  kvb  = sym<float>(g_kv);
    __half* kkb  = sym<__half>(g_kk);
    __half* xt   = sym<__half>(g_xt);
    __half* wkt  = sym<__half>(g_wkt);
    __half* wvt  = sym<__half>(g_wvt);
    __half* wrt  = sym<__half>(g_wrt);
    __half* wot  = sym<__half>(g_wot);
    __half* wst  = sym<__half>(g_wst);
    __half* fwrt = sym<__half>(g_fwrt);
    __half* fwkt = sym<__half>(g_fwkt);
    __half* fwvt = sym<__half>(g_fwvt);

    cudaFuncSetAttribute(gemm_tc<0>, cudaFuncAttributeMaxDynamicSharedMemorySize, GEMM_SMEM);
    cudaFuncSetAttribute(gemm_tc<1>, cudaFuncAttributeMaxDynamicSharedMemorySize, GEMM_SMEM);
    cudaFuncSetAttribute(gemm_tc<2>, cudaFuncAttributeMaxDynamicSharedMemorySize, GEMM_SMEM);
    cudaFuncSetAttribute(gemm_tc<3>, cudaFuncAttributeMaxDynamicSharedMemorySize, GEMM_SMEM);
    cudaFuncSetAttribute(gemm_tc<4>, cudaFuncAttributeMaxDynamicSharedMemorySize, GEMM_SMEM);

    const dim3 blk(256);
    const dim3 grid_elem((unsigned)((S_ + 255) / 256));
    const dim3 grid_gC(C_ / BN, M_ / BM);   // (8, 128)
    const dim3 grid_gF(F_ / BN, M_ / BM);   // (32, 128)

    // --- half pre-conversion (weights + x) ---
    const int nCC4 = (int)(CC_ / 4), nFC4 = (int)(FC_ / 4), nS4 = (int)(S_ / 4);
    cvt_kernel<<<(nS4 + 255) / 256, blk>>>(x, xt, nS4);
    cvt_kernel<<<(nCC4 + 255) / 256, blk>>>(Wk, wkt, nCC4);
    cvt_kernel<<<(nCC4 + 255) / 256, blk>>>(Wv, wvt, nCC4);
    cvt_kernel<<<(nCC4 + 255) / 256, blk>>>(Wr, wrt, nCC4);
    cvt_kernel<<<(nCC4 + 255) / 256, blk>>>(Wo, wot, nCC4);
    cvt_kernel<<<(nCC4 + 255) / 256, blk>>>(shortW, wst, nCC4);
    cvt_kernel<<<(nCC4 + 255) / 256, blk>>>(fWr, fwrt, nCC4);
    cvt_kernel<<<(nFC4 + 255) / 256, blk>>>(fWk, fwkt, nFC4);
    cvt_kernel<<<(nFC4 + 255) / 256, blk>>>(fWv, fwvt, nFC4);

    // --- TimeMix path ---
    ln_kernel<<<M_, blk>>>(x, ln1_w, ln1_b, h);
    mix3_kernel<<<grid_elem, blk>>>(h, mix_k, mix_v, mix_r, xk, xv, xr);
    gemm_tc<0><<<grid_gC, blk, GEMM_SMEM>>>(xk, wkt, kbuf, nullptr, nullptr, C_, C_);
    gemm_tc<0><<<grid_gC, blk, GEMM_SMEM>>>(xv, wvt, vbuf, nullptr, nullptr, C_, C_);
    gemm_tc<1><<<grid_gC, blk, GEMM_SMEM>>>(xr, wrt, rbuf, nullptr, nullptr, C_, C_);
    wkv_part<<<(NCHAN * NCH) / 256, blk>>>(t_decay, kbuf, vbuf);
    wkv_scan<<<NCHAN / 256, blk>>>(t_decay);
    wkv_out<<<(NCHAN * NCH) / 256, blk>>>(t_decay, t_first, kbuf, vbuf, rbuf, rwkv);
    gemm_tc<0><<<grid_gC, blk, GEMM_SMEM>>>(xt, wst, shrt, nullptr, nullptr, C_, C_);
    gemm_tc<3><<<grid_gC, blk, GEMM_SMEM>>>(rwkv, wot, x2, shrt, nullptr, C_, C_);

    // --- ChannelMix path ---
    ln_kernel<<<M_, blk>>>(x2, ln2_w, ln2_b, gbuf);
    mix2_kernel<<<grid_elem, blk>>>(gbuf, fmix_k, fmix_r, gk, gr);
    gemm_tc<2><<<grid_gF, blk, GEMM_SMEM>>>(gk, fwkt, kkb, nullptr, nullptr, F_, C_);
    gemm_tc<0><<<grid_gC, blk, GEMM_SMEM>>>(kkb, fwvt, kvb, nullptr, nullptr, C_, F_);
    gemm_tc<4><<<grid_gC, blk, GEMM_SMEM>>>(gr, fwrt, out, x2, kvb, C_, C_);
}

// round 8
// speedup vs baseline: 2.5424x; 1.1381x over previous
#include <cuda_runtime.h>
#include <cuda_fp16.h>
#include <math.h>
#include <stdint.h>

// Problem dims (fixed by the reference)
#define B_ 8
#define T_ 2048
#define C_ 1024
#define F_ 4096
#define M_ (B_ * T_)   // 16384 rows

constexpr size_t S_  = (size_t)M_ * C_;   // 16,777,216
constexpr size_t SF_ = (size_t)M_ * F_;   // 67,108,864
constexpr size_t CC_ = (size_t)C_ * C_;
constexpr size_t FC_ = (size_t)F_ * C_;

#define NCH 16            // WKV chunks
#define CHL (T_ / NCH)    // 128 steps per chunk
#define NCHAN (B_ * C_)   // 8192 channels

// ---------------------------------------------------------------------------
// Scratch (static device globals — allocation-free per harness rules)
// ---------------------------------------------------------------------------
__device__ float  g_h[S_];
__device__ __half g_xk[S_];
__device__ __half g_xv[S_];
__device__ __half g_xr[S_];
__device__ float  g_k[S_];      // wkv inputs stay fp32
__device__ float  g_v[S_];
__device__ float  g_r[S_];
__device__ __half g_rwkv[S_];   // GEMM input -> half
__device__ float  g_short[S_];
__device__ float  g_x2[S_];
__device__ float  g_g[S_];
__device__ __half g_gk[S_];
__device__ __half g_gr[S_];
__device__ float  g_kv[S_];
__device__ __half g_kk[SF_];    // GEMM input -> half
__device__ __half g_xt[S_];     // half copy of x
// half weights
__device__ __half g_wkt[CC_];
__device__ __half g_wvt[CC_];
__device__ __half g_wrt[CC_];
__device__ __half g_wot[CC_];
__device__ __half g_wst[CC_];
__device__ __half g_fwrt[CC_];
__device__ __half g_fwkt[FC_];
__device__ __half g_fwvt[FC_];
// WKV chunk-scan state
__device__ float g_sa[NCHAN * NCH], g_sbv[NCHAN * NCH], g_sp[NCHAN * NCH];
__device__ float g_pa[NCHAN * NCH], g_pbv[NCHAN * NCH], g_pp[NCHAN * NCH];

// ---------------------------------------------------------------------------
// helpers
// ---------------------------------------------------------------------------
__device__ __forceinline__ void cp_async16(void* smem, const void* gmem) {
    uint32_t s = (uint32_t)__cvta_generic_to_shared(smem);
    asm volatile("cp.async.cg.shared.global [%0], [%1], 16;" :: "r"(s), "l"(gmem));
}
#define CP_COMMIT() asm volatile("cp.async.commit_group;")
#define CP_WAIT0()  asm volatile("cp.async.wait_group 0;")
#define CP_WAIT1()  asm volatile("cp.async.wait_group 1;")

// fp16 mma with fp32 accumulate: D(16x8) += A(16x16) * B(16x8)
__device__ __forceinline__ void mma_f16(float* d, const uint32_t* a, const uint32_t* b) {
    asm volatile(
        "mma.sync.aligned.m16n8k16.row.col.f32.f16.f16.f32 "
        "{%0,%1,%2,%3}, {%4,%5,%6,%7}, {%8,%9}, {%0,%1,%2,%3};"
        : "+f"(d[0]), "+f"(d[1]), "+f"(d[2]), "+f"(d[3])
        : "r"(a[0]), "r"(a[1]), "r"(a[2]), "r"(a[3]),
          "r"(b[0]), "r"(b[1]));
}

__device__ __forceinline__ void ldsm_x4(uint32_t* r, uint32_t addr) {
    asm volatile("ldmatrix.sync.aligned.m8n8.x4.shared.b16 {%0,%1,%2,%3}, [%4];"
        : "=r"(r[0]), "=r"(r[1]), "=r"(r[2]), "=r"(r[3]) : "r"(addr));
}

// ---------------------------------------------------------------------------
// float -> half copy-convert (weights + x)
// ---------------------------------------------------------------------------
__global__ void __launch_bounds__(256) cvt_kernel(const float* __restrict__ src,
                                                  __half* __restrict__ dst,
                                                  int n4) {
    int i = blockIdx.x * blockDim.x + threadIdx.x;
    if (i >= n4) return;
    float4 v = ((const float4*)src)[i];
    __half2 h0 = __floats2half2_rn(v.x, v.y);
    __half2 h1 = __floats2half2_rn(v.z, v.w);
    uint2 o;
    o.x = *(uint32_t*)&h0;
    o.y = *(uint32_t*)&h1;
    ((uint2*)dst)[i] = o;
}

// ---------------------------------------------------------------------------
// LayerNorm over last dim (C=1024). 256 thr per row, one float4 per thread.
// ---------------------------------------------------------------------------
__global__ void __launch_bounds__(256) ln_kernel(const float* __restrict__ x,
                                                 const float* __restrict__ w,
                                                 const float* __restrict__ b,
                                                 float* __restrict__ out) {
    const size_t row = blockIdx.x;
    const float4* xr = (const float4*)(x + row * C_);
    const int tid = threadIdx.x;

    float4 xv = xr[tid];
    float s  = xv.x + xv.y + xv.z + xv.w;
    float ss = xv.x * xv.x + xv.y * xv.y + xv.z * xv.z + xv.w * xv.w;

    #pragma unroll
    for (int o = 16; o > 0; o >>= 1) {
        s  += __shfl_down_sync(0xffffffffu, s,  o);
        ss += __shfl_down_sync(0xffffffffu, ss, o);
    }
    __shared__ float sm_s[8], sm_ss[8];
    int wid = tid >> 5, lid = tid & 31;
    if (lid == 0) { sm_s[wid] = s; sm_ss[wid] = ss; }
    __syncthreads();
    if (wid == 0) {
        s  = (lid < 8) ? sm_s[lid]  : 0.f;
        ss = (lid < 8) ? sm_ss[lid] : 0.f;
        #pragma unroll
        for (int o = 4; o > 0; o >>= 1) {
            s  += __shfl_down_sync(0xffffffffu, s,  o);
            ss += __shfl_down_sync(0xffffffffu, ss, o);
        }
        if (lid == 0) { sm_s[0] = s; sm_ss[0] = ss; }
    }
    __syncthreads();
    const float mean = sm_s[0] * (1.0f / C_);
    const float var  = sm_ss[0] * (1.0f / C_) - mean * mean;
    const float rstd = rsqrtf(var + 1e-5f);

    float4 wv = ((const float4*)w)[tid];
    float4 bv = ((const float4*)b)[tid];
    float4 ov;
    ov.x = (xv.x - mean) * rstd * wv.x + bv.x;
    ov.y = (xv.y - mean) * rstd * wv.y + bv.y;
    ov.z = (xv.z - mean) * rstd * wv.z + bv.z;
    ov.w = (xv.w - mean) * rstd * wv.w + bv.w;
    ((float4*)(out + row * C_))[tid] = ov;
}

// ---------------------------------------------------------------------------
// Time-shift + mix (vectorized x4); outputs half (GEMM inputs)
// ---------------------------------------------------------------------------
__device__ __forceinline__ uint2 mix4(const float4& hc, const float4& hh,
                                      const float4& m) {
    float o0 = hc.x * m.x + hh.x * (1.f - m.x);
    float o1 = hc.y * m.y + hh.y * (1.f - m.y);
    float o2 = hc.z * m.z + hh.z * (1.f - m.z);
    float o3 = hc.w * m.w + hh.w * (1.f - m.w);
    __half2 p0 = __floats2half2_rn(o0, o1);
    __half2 p1 = __floats2half2_rn(o2, o3);
    uint2 r;
    r.x = *(uint32_t*)&p0;
    r.y = *(uint32_t*)&p1;
    return r;
}

__global__ void __launch_bounds__(256) mix3_kernel(const float* __restrict__ h,
                                                   const float* __restrict__ mk,
                                                   const float* __restrict__ mv,
                                                   const float* __restrict__ mr,
                                                   __half* __restrict__ xk,
                                                   __half* __restrict__ xv,
                                                   __half* __restrict__ xr) {
    size_t i4 = (size_t)blockIdx.x * blockDim.x + threadIdx.x;  // S_/4 total
    if (i4 >= S_ / 4) return;
    const int c4 = (int)(i4 & (C_ / 4 - 1));          // float4 index in row
    const size_t row = i4 >> 8;                       // C_/4 = 256
    const int t = (int)(row & (T_ - 1));
    float4 hc = ((const float4*)h)[i4];
    float4 hh = (t == 0) ? make_float4(0.f, 0.f, 0.f, 0.f)
                         : ((const float4*)h)[i4 - C_ / 4];
    ((uint2*)xk)[i4] = mix4(hc, hh, ((const float4*)mk)[c4]);
    ((uint2*)xv)[i4] = mix4(hc, hh, ((const float4*)mv)[c4]);
    ((uint2*)xr)[i4] = mix4(hc, hh, ((const float4*)mr)[c4]);
}

__global__ void __launch_bounds__(256) mix2_kernel(const float* __restrict__ h,
                                                   const float* __restrict__ mk,
                                                   const float* __restrict__ mr,
                                                   __half* __restrict__ xk,
                                                   __half* __restrict__ xr) {
    size_t i4 = (size_t)blockIdx.x * blockDim.x + threadIdx.x;
    if (i4 >= S_ / 4) return;
    const int c4 = (int)(i4 & (C_ / 4 - 1));
    const size_t row = i4 >> 8;
    const int t = (int)(row & (T_ - 1));
    float4 hc = ((const float4*)h)[i4];
    float4 hh = (t == 0) ? make_float4(0.f, 0.f, 0.f, 0.f)
                         : ((const float4*)h)[i4 - C_ / 4];
    ((uint2*)xk)[i4] = mix4(hc, hh, ((const float4*)mk)[c4]);
    ((uint2*)xr)[i4] = mix4(hc, hh, ((const float4*)mr)[c4]);
}

// ---------------------------------------------------------------------------
// WKV chunk-parallel scan (3 passes). fp32 in, half out (feeds Wo GEMM).
// ---------------------------------------------------------------------------
__global__ void __launch_bounds__(256) wkv_part(const float* __restrict__ decay,
                                                const float* __restrict__ k,
                                                const float* __restrict__ v) {
    int gid = blockIdx.x * blockDim.x + threadIdx.x;  // 131072
    int j    = gid >> 13;          // chunk 0..15
    int chan = gid & (NCHAN - 1);  // 0..8191
    int b = chan >> 10;
    int c = chan & (C_ - 1);
    const float w = -__expf(decay[c]);
    size_t off = ((size_t)b * T_ + (size_t)j * CHL) * C_ + c;

    float a = 0.f, bb = 0.f, p = -1e30f;
    #pragma unroll 4
    for (int t = 0; t < CHL; ++t, off += C_) {
        const float kt = k[off];
        const float vt = v[off];
        const float ww2 = p + w;
        const float q2  = fmaxf(ww2, kt);
        const float f1  = __expf(ww2 - q2);
        const float f2  = __expf(kt - q2);
        a  = f1 * a + f2 * vt;
        bb = f1 * bb + f2;
        p  = q2;
    }
    g_sa[j * NCHAN + chan]  = a;
    g_sbv[j * NCHAN + chan] = bb;
    g_sp[j * NCHAN + chan]  = p;
}

__global__ void __launch_bounds__(256) wkv_scan(const float* __restrict__ decay) {
    int chan = blockIdx.x * blockDim.x + threadIdx.x;  // 8192
    if (chan >= NCHAN) return;
    int c = chan & (C_ - 1);
    const float w = -__expf(decay[c]);
    const float Lw = (float)CHL * w;

    float a = 0.f, bb = 0.f, p = -1e30f;
    #pragma unroll
    for (int j = 0; j < NCH; ++j) {
        g_pa[j * NCHAN + chan]  = a;
        g_pbv[j * NCHAN + chan] = bb;
        g_pp[j * NCHAN + chan]  = p;
        const float ca = g_sa[j * NCHAN + chan];
        const float cb = g_sbv[j * NCHAN + chan];
        const float cp = g_sp[j * NCHAN + chan];
        const float pw = p + Lw;
        const float q  = fmaxf(pw, cp);
        const float e0 = __expf(pw - q);
        const float e1 = __expf(cp - q);
        a  = a * e0 + ca * e1;
        bb = bb * e0 + cb * e1;
        p  = q;
    }
}

__global__ void __launch_bounds__(256) wkv_out(const float* __restrict__ decay,
                                               const float* __restrict__ first,
                                               const float* __restrict__ k,
                                               const float* __restrict__ v,
                                               const float* __restrict__ r,
                                               __half* __restrict__ out) {
    int gid = blockIdx.x * blockDim.x + threadIdx.x;
    int j    = gid >> 13;
    int chan = gid & (NCHAN - 1);
    int b = chan >> 10;
    int c = chan & (C_ - 1);
    const float w = -__expf(decay[c]);
    const float u = first[c];
    size_t off = ((size_t)b * T_ + (size_t)j * CHL) * C_ + c;

    float a  = g_pa[j * NCHAN + chan];
    float bb = g_pbv[j * NCHAN + chan];
    float p  = g_pp[j * NCHAN + chan];

    #pragma unroll 4
    for (int t = 0; t < CHL; ++t, off += C_) {
        const float kt = k[off];
        const float vt = v[off];
        const float ww = u + kt;
        const float q  = fmaxf(p, ww);
        const float e1 = __expf(p - q);
        const float e2 = __expf(ww - q);
        const float y  = (e1 * a + e2 * vt) / (e1 * bb + e2);
        out[off] = __float2half_rn(y * r[off]);
        const float ww2 = p + w;
        const float q2  = fmaxf(ww2, kt);
        const float f1  = __expf(ww2 - q2);
        const float f2  = __expf(kt - q2);
        a  = f1 * a + f2 * vt;
        bb = f1 * bb + f2;
        p  = q2;
    }
}

// ---------------------------------------------------------------------------
// fp16 tensor-core GEMM:  C[M,N] = A[M,K] * W[N,K]^T   (A, W half; fp32 acc)
// 128x128 CTA tile, BK=32 (halfs), 256 threads (8 warps @ 64x32),
// 3-stage cp.async pipeline, 2 CTAs/SM, ldmatrix fragment loads.
// MODE: 0 = store f32, 1 = sigmoid f32, 2 = relu^2 -> half, 3 = +aux1 f32,
//       4 = aux1 + sigmoid(acc)*aux2 f32
// ---------------------------------------------------------------------------
#define BM 128
#define BN 128
#define BK 32            // halfs per stage in K
#define BKPH 40          // padded halfs per row (80B, 16B-aligned rows)
#define STG 3
#define STAGE_HALFS (128 * BKPH)
#define GEMM_SMEM (STG * STAGE_HALFS * 2 * 2)   // 61440 bytes

template <int MODE>
__global__ void __launch_bounds__(256, 2) gemm_tc(const __half* __restrict__ A,
                                                  const __half* __restrict__ W,
                                                  void* __restrict__ Cc,
                                                  const float* __restrict__ aux1,
                                                  const float* __restrict__ aux2,
                                                  int N, int K) {
    extern __shared__ __half smh[];
    __half* AsBase = smh;                       // [STG][128][BKPH]
    __half* BsBase = smh + STG * STAGE_HALFS;   // [STG][128][BKPH]

    const int tid  = threadIdx.x;
    const int wid  = tid >> 5;
    const int lane = tid & 31;
    const int g    = lane >> 2;   // 0..7
    const int tig  = lane & 3;    // 0..3

    const int warp_m = wid >> 2;  // 0..1 -> 64 rows
    const int warp_n = wid & 3;   // 0..3 -> 32 cols

    const size_t brow = blockIdx.y;
    const size_t bcol = blockIdx.x;

    // loader: 2 threads per row; each loads 2 x 16B (16 halfs)
    const int lrow = tid >> 1;           // 0..127
    const int lk   = (tid & 1) * 16;     // 0 or 16 (halfs)

    const __half* Ag = A + (brow * BM + lrow) * (size_t)K + lk;
    const __half* Wg = W + (bcol * BN + lrow) * (size_t)K + lk;

    // ldmatrix per-lane base addresses (byte offsets in shared space)
    const uint32_t smA = (uint32_t)__cvta_generic_to_shared(AsBase);
    const uint32_t smB = (uint32_t)__cvta_generic_to_shared(BsBase);
    // A x4: lanes 0-7 rows0-7 k0 | 8-15 rows8-15 k0 | 16-23 rows0-7 k8 | 24-31 rows8-15 k8
    const uint32_t aBase = smA +
        (((uint32_t)(warp_m * 64 + (lane & 15)) * BKPH + (uint32_t)(lane >> 4) * 8) << 1);
    // B x4 (two n8k16 tiles): lanes 0-7 n0-7 k0 | 8-15 n0-7 k8 | 16-23 n8-15 k0 | 24-31 n8-15 k8
    const uint32_t bBase = smB +
        (((uint32_t)(warp_n * 32 + ((lane >> 4) << 3) + (lane & 7)) * BKPH +
          (uint32_t)((lane >> 3) & 1) * 8) << 1);

    float acc[4][4][4];
    #pragma unroll
    for (int i = 0; i < 4; ++i)
        #pragma unroll
        for (int j = 0; j < 4; ++j)
            #pragma unroll
            for (int r = 0; r < 4; ++r) acc[i][j][r] = 0.f;

    auto load_stage = [&](int s, int k0) {
        __half* a = AsBase + s * STAGE_HALFS + lrow * BKPH + lk;
        __half* b = BsBase + s * STAGE_HALFS + lrow * BKPH + lk;
        cp_async16(a,     Ag + k0);
        cp_async16(a + 8, Ag + k0 + 8);
        cp_async16(b,     Wg + k0);
        cp_async16(b + 8, Wg + k0 + 8);
    };

    load_stage(0, 0); CP_COMMIT();
    load_stage(1, BK); CP_COMMIT();

    const int nk = K / BK;
    for (int it = 0; it < nk; ++it) {
        const int cur = it % 3;
        if (it == nk - 1) { CP_WAIT0(); } else { CP_WAIT1(); }
        __syncthreads();

        const uint32_t soff = (uint32_t)cur * (STAGE_HALFS * 2);

        #pragma unroll
        for (int ks = 0; ks < 2; ++ks) {
            const uint32_t koff = (uint32_t)ks * 32;   // 16 halfs
            uint32_t af[4][4];
            uint32_t b0[4], b1[4];
            ldsm_x4(b0, bBase + soff + koff);                 // nt0, nt1
            ldsm_x4(b1, bBase + soff + koff + 16 * BKPH * 2); // nt2, nt3
            #pragma unroll
            for (int mt = 0; mt < 4; ++mt)
                ldsm_x4(af[mt], aBase + soff + koff + (uint32_t)mt * (16 * BKPH * 2));
            #pragma unroll
            for (int mt = 0; mt < 4; ++mt) {
                mma_f16(acc[mt][0], af[mt], b0);
                mma_f16(acc[mt][1], af[mt], b0 + 2);
                mma_f16(acc[mt][2], af[mt], b1);
                mma_f16(acc[mt][3], af[mt], b1 + 2);
            }
        }

        if (it + 2 < nk) {
            load_stage((it + 2) % 3, (it + 2) * BK);
            CP_COMMIT();
        }
    }

    // Epilogue
    #pragma unroll
    for (int mt = 0; mt < 4; ++mt) {
        const int r0 = (int)(brow * BM) + warp_m * 64 + mt * 16 + g;
        #pragma unroll
        for (int nt = 0; nt < 4; ++nt) {
            const int c0 = (int)(bcol * BN) + warp_n * 32 + nt * 8 + 2 * tig;
            #pragma unroll
            for (int half_i = 0; half_i < 2; ++half_i) {
                const int row = r0 + half_i * 8;
                const size_t off = (size_t)row * N + c0;
                float v0 = acc[mt][nt][half_i * 2 + 0];
                float v1 = acc[mt][nt][half_i * 2 + 1];
                if (MODE == 1) {
                    v0 = 1.f / (1.f + __expf(-v0));
                    v1 = 1.f / (1.f + __expf(-v1));
                } else if (MODE == 2) {
                    v0 = fmaxf(v0, 0.f); v0 = v0 * v0;
                    v1 = fmaxf(v1, 0.f); v1 = v1 * v1;
                } else if (MODE == 3) {
                    float2 a1 = *(const float2*)(aux1 + off);
                    v0 += a1.x; v1 += a1.y;
                } else if (MODE == 4) {
                    float2 a1 = *(const float2*)(aux1 + off);
                    float2 a2 = *(const float2*)(aux2 + off);
                    v0 = a1.x + (1.f / (1.f + __expf(-v0))) * a2.x;
                    v1 = a1.y + (1.f / (1.f + __expf(-v1))) * a2.y;
                }
                if (MODE == 2) {
                    __half2 hv = __floats2half2_rn(v0, v1);
                    *(__half2*)((__half*)Cc + off) = hv;
                } else {
                    float2 o; o.x = v0; o.y = v1;
                    *(float2*)((float*)Cc + off) = o;
                }
            }
        }
    }
}

// ---------------------------------------------------------------------------
// Launch
// ---------------------------------------------------------------------------
template <typename T>
static T* sym(const void* s) {
    void* p = nullptr;
    cudaGetSymbolAddress(&p, s);
    return (T*)p;
}

extern "C" void kernel_launch(void* const* d_in, const int* in_sizes, int n_in,
                              void* d_out, int out_size) {
    const float* x        = (const float*)d_in[0];
    const float* ln1_w    = (const float*)d_in[1];
    const float* ln1_b    = (const float*)d_in[2];
    const float* ln2_w    = (const float*)d_in[3];
    const float* ln2_b    = (const float*)d_in[4];
    const float* t_decay  = (const float*)d_in[5];
    const float* t_first  = (const float*)d_in[6];
    const float* mix_k    = (const float*)d_in[7];
    const float* mix_v    = (const float*)d_in[8];
    const float* mix_r    = (const float*)d_in[9];
    const float* Wk       = (const float*)d_in[10];
    const float* Wv       = (const float*)d_in[11];
    const float* Wr       = (const float*)d_in[12];
    const float* Wo       = (const float*)d_in[13];
    const float* fmix_k   = (const float*)d_in[14];
    const float* fmix_r   = (const float*)d_in[15];
    const float* fWk      = (const float*)d_in[16];   // [F, C]
    const float* fWr      = (const float*)d_in[17];   // [C, C]
    const float* fWv      = (const float*)d_in[18];   // [C, F]
    const float* shortW   = (const float*)d_in[19];
    float* out = (float*)d_out;

    float*  h    = sym<float>(g_h);
    __half* xk   = sym<__half>(g_xk);
    __half* xv   = sym<__half>(g_xv);
    __half* xr   = sym<__half>(g_xr);
    float*  kbuf = sym<float>(g_k);
    float*  vbuf = sym<float>(g_v);
    float*  rbuf = sym<float>(g_r);
    __half* rwkv = sym<__half>(g_rwkv);
    float*  shrt = sym<float>(g_short);
    float*  x2   = sym<float>(g_x2);
    float*  gbuf = sym<float>(g_g);
    __half* gk   = sym<__half>(g_gk);
    __half* gr   = sym<__half>(g_gr);
    float*  kvb  = sym<float>(g_kv);
    __half* kkb  = sym<__half>(g_kk);
    __half* xt   = sym<__half>(g_xt);
    __half* wkt  = sym<__half>(g_wkt);
    __half* wvt  = sym<__half>(g_wvt);
    __half* wrt  = sym<__half>(g_wrt);
    __half* wot  = sym<__half>(g_wot);
    __half* wst  = sym<__half>(g_wst);
    __half* fwrt = sym<__half>(g_fwrt);
    __half* fwkt = sym<__half>(g_fwkt);
    __half* fwvt = sym<__half>(g_fwvt);

    cudaFuncSetAttribute(gemm_tc<0>, cudaFuncAttributeMaxDynamicSharedMemorySize, GEMM_SMEM);
    cudaFuncSetAttribute(gemm_tc<1>, cudaFuncAttributeMaxDynamicSharedMemorySize, GEMM_SMEM);
    cudaFuncSetAttribute(gemm_tc<2>, cudaFuncAttributeMaxDynamicSharedMemorySize, GEMM_SMEM);
    cudaFuncSetAttribute(gemm_tc<3>, cudaFuncAttributeMaxDynamicSharedMemorySize, GEMM_SMEM);
    cudaFuncSetAttribute(gemm_tc<4>, cudaFuncAttributeMaxDynamicSharedMemorySize, GEMM_SMEM);

    const dim3 blk(256);
    const dim3 grid_vec4((unsigned)((S_ / 4 + 255) / 256));
    const dim3 grid_gC(C_ / BN, M_ / BM);   // (8, 128)
    const dim3 grid_gF(F_ / BN, M_ / BM);   // (32, 128)

    // --- half pre-conversion (weights + x) ---
    const int nCC4 = (int)(CC_ / 4), nFC4 = (int)(FC_ / 4), nS4 = (int)(S_ / 4);
    cvt_kernel<<<(nS4 + 255) / 256, blk>>>(x, xt, nS4);
    cvt_kernel<<<(nCC4 + 255) / 256, blk>>>(Wk, wkt, nCC4);
    cvt_kernel<<<(nCC4 + 255) / 256, blk>>>(Wv, wvt, nCC4);
    cvt_kernel<<<(nCC4 + 255) / 256, blk>>>(Wr, wrt, nCC4);
    cvt_kernel<<<(nCC4 + 255) / 256, blk>>>(Wo, wot, nCC4);
    cvt_kernel<<<(nCC4 + 255) / 256, blk>>>(shortW, wst, nCC4);
    cvt_kernel<<<(nCC4 + 255) / 256, blk>>>(fWr, fwrt, nCC4);
    cvt_kernel<<<(nFC4 + 255) / 256, blk>>>(fWk, fwkt, nFC4);
    cvt_kernel<<<(nFC4 + 255) / 256, blk>>>(fWv, fwvt, nFC4);

    // --- TimeMix path ---
    ln_kernel<<<M_, blk>>>(x, ln1_w, ln1_b, h);
    mix3_kernel<<<grid_vec4, blk>>>(h, mix_k, mix_v, mix_r, xk, xv, xr);
    gemm_tc<0><<<grid_gC, blk, GEMM_SMEM>>>(xk, wkt, kbuf, nullptr, nullptr, C_, C_);
    gemm_tc<0><<<grid_gC, blk, GEMM_SMEM>>>(xv, wvt, vbuf, nullptr, nullptr, C_, C_);
    gemm_tc<1><<<grid_gC, blk, GEMM_SMEM>>>(xr, wrt, rbuf, nullptr, nullptr, C_, C_);
    wkv_part<<<(NCHAN * NCH) / 256, blk>>>(t_decay, kbuf, vbuf);
    wkv_scan<<<NCHAN / 256, blk>>>(t_decay);
    wkv_out<<<(NCHAN * NCH) / 256, blk>>>(t_decay, t_first, kbuf, vbuf, rbuf, rwkv);
    gemm_tc<0><<<grid_gC, blk, GEMM_SMEM>>>(xt, wst, shrt, nullptr, nullptr, C_, C_);
    gemm_tc<3><<<grid_gC, blk, GEMM_SMEM>>>(rwkv, wot, x2, shrt, nullptr, C_, C_);

    // --- ChannelMix path ---
    ln_kernel<<<M_, blk>>>(x2, ln2_w, ln2_b, gbuf);
    mix2_kernel<<<grid_vec4, blk>>>(gbuf, fmix_k, fmix_r, gk, gr);
    gemm_tc<2><<<grid_gF, blk, GEMM_SMEM>>>(gk, fwkt, kkb, nullptr, nullptr, F_, C_);
    gemm_tc<0><<<grid_gC, blk, GEMM_SMEM>>>(kkb, fwvt, kvb, nullptr, nullptr, C_, F_);
    gemm_tc<4><<<grid_gC, blk, GEMM_SMEM>>>(gr, fwrt, out, x2, kvb, C_, C_);
}

// round 9
// speedup vs baseline: 2.6457x; 1.0406x over previous
#include <cuda_runtime.h>
#include <cuda_fp16.h>
#include <math.h>
#include <stdint.h>

// Problem dims (fixed by the reference)
#define B_ 8
#define T_ 2048
#define C_ 1024
#define F_ 4096
#define M_ (B_ * T_)   // 16384 rows

constexpr size_t S_  = (size_t)M_ * C_;   // 16,777,216
constexpr size_t SF_ = (size_t)M_ * F_;   // 67,108,864
constexpr size_t CC_ = (size_t)C_ * C_;
constexpr size_t FC_ = (size_t)F_ * C_;

#define NCH 16            // WKV chunks
#define CHL (T_ / NCH)    // 128 steps per chunk
#define NCHAN (B_ * C_)   // 8192 channels

// ---------------------------------------------------------------------------
// Scratch (static device globals — allocation-free per harness rules)
// ---------------------------------------------------------------------------
__device__ float  g_h[S_];
__device__ __half g_xk[S_];
__device__ __half g_xv[S_];
__device__ __half g_xr[S_];
__device__ float  g_ek[S_];     // exp(k)  (from Wk GEMM epilogue)
__device__ float  g_v[S_];
__device__ float  g_r[S_];      // sigmoid(r)
__device__ __half g_ao[(size_t)M_ * 2048];  // [rwkv | x_half] along K
__device__ float  g_x2[S_];
__device__ float  g_g[S_];
__device__ __half g_gk[S_];
__device__ __half g_gr[S_];
__device__ float  g_kv[S_];
__device__ __half g_kk[SF_];
// half weights
__device__ __half g_wkt[CC_];
__device__ __half g_wvt[CC_];
__device__ __half g_wrt[CC_];
__device__ __half g_wos[2 * CC_];  // [Wo | shortW] along K
__device__ __half g_fwrt[CC_];
__device__ __half g_fwkt[FC_];
__device__ __half g_fwvt[FC_];
// WKV chunk-scan state (a, b per chunk)
__device__ float g_sa[NCHAN * NCH], g_sb[NCHAN * NCH];
__device__ float g_pa[NCHAN * NCH], g_pb[NCHAN * NCH];

// ---------------------------------------------------------------------------
// helpers
// ---------------------------------------------------------------------------
__device__ __forceinline__ void cp_async16(void* smem, const void* gmem) {
    uint32_t s = (uint32_t)__cvta_generic_to_shared(smem);
    asm volatile("cp.async.cg.shared.global [%0], [%1], 16;" :: "r"(s), "l"(gmem));
}
#define CP_COMMIT() asm volatile("cp.async.commit_group;")
#define CP_WAIT0()  asm volatile("cp.async.wait_group 0;")
#define CP_WAIT1()  asm volatile("cp.async.wait_group 1;")

__device__ __forceinline__ void mma_f16(float* d, const uint32_t* a, const uint32_t* b) {
    asm volatile(
        "mma.sync.aligned.m16n8k16.row.col.f32.f16.f16.f32 "
        "{%0,%1,%2,%3}, {%4,%5,%6,%7}, {%8,%9}, {%0,%1,%2,%3};"
        : "+f"(d[0]), "+f"(d[1]), "+f"(d[2]), "+f"(d[3])
        : "r"(a[0]), "r"(a[1]), "r"(a[2]), "r"(a[3]),
          "r"(b[0]), "r"(b[1]));
}

__device__ __forceinline__ void ldsm_x4(uint32_t* r, uint32_t addr) {
    asm volatile("ldmatrix.sync.aligned.m8n8.x4.shared.b16 {%0,%1,%2,%3}, [%4];"
        : "=r"(r[0]), "=r"(r[1]), "=r"(r[2]), "=r"(r[3]) : "r"(addr));
}

// ---------------------------------------------------------------------------
// float -> half copy-convert (plain, contiguous)
// ---------------------------------------------------------------------------
__global__ void __launch_bounds__(256) cvt_kernel(const float* __restrict__ src,
                                                  __half* __restrict__ dst,
                                                  int n4) {
    int i = blockIdx.x * blockDim.x + threadIdx.x;
    if (i >= n4) return;
    float4 v = ((const float4*)src)[i];
    __half2 h0 = __floats2half2_rn(v.x, v.y);
    __half2 h1 = __floats2half2_rn(v.z, v.w);
    uint2 o;
    o.x = *(uint32_t*)&h0;
    o.y = *(uint32_t*)&h1;
    ((uint2*)dst)[i] = o;
}

// float -> half into a row-strided buffer: dst row stride 2048 halfs,
// source rows are C_=1024 floats. off_u2 in uint2 (4-half) units.
__global__ void __launch_bounds__(256) cvt_strided(const float* __restrict__ src,
                                                   __half* __restrict__ dst,
                                                   int n4, int off_u2) {
    int i4 = blockIdx.x * blockDim.x + threadIdx.x;
    if (i4 >= n4) return;
    int row = i4 >> 8;        // / (C_/4)
    int col = i4 & 255;
    float4 v = ((const float4*)src)[i4];
    __half2 h0 = __floats2half2_rn(v.x, v.y);
    __half2 h1 = __floats2half2_rn(v.z, v.w);
    uint2 o;
    o.x = *(uint32_t*)&h0;
    o.y = *(uint32_t*)&h1;
    ((uint2*)dst)[(size_t)row * 512 + off_u2 + col] = o;
}

// ---------------------------------------------------------------------------
// LayerNorm over last dim (C=1024). 256 thr per row, one float4 per thread.
// ---------------------------------------------------------------------------
__global__ void __launch_bounds__(256) ln_kernel(const float* __restrict__ x,
                                                 const float* __restrict__ w,
                                                 const float* __restrict__ b,
                                                 float* __restrict__ out) {
    const size_t row = blockIdx.x;
    const float4* xr = (const float4*)(x + row * C_);
    const int tid = threadIdx.x;

    float4 xv = xr[tid];
    float s  = xv.x + xv.y + xv.z + xv.w;
    float ss = xv.x * xv.x + xv.y * xv.y + xv.z * xv.z + xv.w * xv.w;

    #pragma unroll
    for (int o = 16; o > 0; o >>= 1) {
        s  += __shfl_down_sync(0xffffffffu, s,  o);
        ss += __shfl_down_sync(0xffffffffu, ss, o);
    }
    __shared__ float sm_s[8], sm_ss[8];
    int wid = tid >> 5, lid = tid & 31;
    if (lid == 0) { sm_s[wid] = s; sm_ss[wid] = ss; }
    __syncthreads();
    if (wid == 0) {
        s  = (lid < 8) ? sm_s[lid]  : 0.f;
        ss = (lid < 8) ? sm_ss[lid] : 0.f;
        #pragma unroll
        for (int o = 4; o > 0; o >>= 1) {
            s  += __shfl_down_sync(0xffffffffu, s,  o);
            ss += __shfl_down_sync(0xffffffffu, ss, o);
        }
        if (lid == 0) { sm_s[0] = s; sm_ss[0] = ss; }
    }
    __syncthreads();
    const float mean = sm_s[0] * (1.0f / C_);
    const float var  = sm_ss[0] * (1.0f / C_) - mean * mean;
    const float rstd = rsqrtf(var + 1e-5f);

    float4 wv = ((const float4*)w)[tid];
    float4 bv = ((const float4*)b)[tid];
    float4 ov;
    ov.x = (xv.x - mean) * rstd * wv.x + bv.x;
    ov.y = (xv.y - mean) * rstd * wv.y + bv.y;
    ov.z = (xv.z - mean) * rstd * wv.z + bv.z;
    ov.w = (xv.w - mean) * rstd * wv.w + bv.w;
    ((float4*)(out + row * C_))[tid] = ov;
}

// ---------------------------------------------------------------------------
// Time-shift + mix (vectorized x4); outputs half (GEMM inputs)
// ---------------------------------------------------------------------------
__device__ __forceinline__ uint2 mix4(const float4& hc, const float4& hh,
                                      const float4& m) {
    float o0 = hc.x * m.x + hh.x * (1.f - m.x);
    float o1 = hc.y * m.y + hh.y * (1.f - m.y);
    float o2 = hc.z * m.z + hh.z * (1.f - m.z);
    float o3 = hc.w * m.w + hh.w * (1.f - m.w);
    __half2 p0 = __floats2half2_rn(o0, o1);
    __half2 p1 = __floats2half2_rn(o2, o3);
    uint2 r;
    r.x = *(uint32_t*)&p0;
    r.y = *(uint32_t*)&p1;
    return r;
}

__global__ void __launch_bounds__(256) mix3_kernel(const float* __restrict__ h,
                                                   const float* __restrict__ mk,
                                                   const float* __restrict__ mv,
                                                   const float* __restrict__ mr,
                                                   __half* __restrict__ xk,
                                                   __half* __restrict__ xv,
                                                   __half* __restrict__ xr) {
    size_t i4 = (size_t)blockIdx.x * blockDim.x + threadIdx.x;
    if (i4 >= S_ / 4) return;
    const int c4 = (int)(i4 & (C_ / 4 - 1));
    const size_t row = i4 >> 8;
    const int t = (int)(row & (T_ - 1));
    float4 hc = ((const float4*)h)[i4];
    float4 hh = (t == 0) ? make_float4(0.f, 0.f, 0.f, 0.f)
                         : ((const float4*)h)[i4 - C_ / 4];
    ((uint2*)xk)[i4] = mix4(hc, hh, ((const float4*)mk)[c4]);
    ((uint2*)xv)[i4] = mix4(hc, hh, ((const float4*)mv)[c4]);
    ((uint2*)xr)[i4] = mix4(hc, hh, ((const float4*)mr)[c4]);
}

__global__ void __launch_bounds__(256) mix2_kernel(const float* __restrict__ h,
                                                   const float* __restrict__ mk,
                                                   const float* __restrict__ mr,
                                                   __half* __restrict__ xk,
                                                   __half* __restrict__ xr) {
    size_t i4 = (size_t)blockIdx.x * blockDim.x + threadIdx.x;
    if (i4 >= S_ / 4) return;
    const int c4 = (int)(i4 & (C_ / 4 - 1));
    const size_t row = i4 >> 8;
    const int t = (int)(row & (T_ - 1));
    float4 hc = ((const float4*)h)[i4];
    float4 hh = (t == 0) ? make_float4(0.f, 0.f, 0.f, 0.f)
                         : ((const float4*)h)[i4 - C_ / 4];
    ((uint2*)xk)[i4] = mix4(hc, hh, ((const float4*)mk)[c4]);
    ((uint2*)xr)[i4] = mix4(hc, hh, ((const float4*)mr)[c4]);
}

// ---------------------------------------------------------------------------
// WKV chunk-parallel scan, UNNORMALIZED form (exp(k) precomputed in GEMM):
//   a_t = ew*a + ek_t*v_t ;  b_t = ew*b + ek_t
//   y_t = (a_{t-1} + eu*ek_t*v_t) / (b_{t-1} + eu*ek_t)
// Values bounded (|k| small, u<0, w<0) -> fp32 safe without p-shift.
// ---------------------------------------------------------------------------
__global__ void __launch_bounds__(256) wkv_part(const float* __restrict__ decay,
                                                const float* __restrict__ ek,
                                                const float* __restrict__ v) {
    int gid = blockIdx.x * blockDim.x + threadIdx.x;  // 131072
    int j    = gid >> 13;
    int chan = gid & (NCHAN - 1);
    int b = chan >> 10;
    int c = chan & (C_ - 1);
    const float ew = __expf(-__expf(decay[c]));
    size_t off = ((size_t)b * T_ + (size_t)j * CHL) * C_ + c;

    float a = 0.f, bb = 0.f;
    #pragma unroll 4
    for (int t = 0; t < CHL; ++t, off += C_) {
        const float e = ek[off];
        const float vt = v[off];
        a  = fmaf(ew, a, e * vt);
        bb = fmaf(ew, bb, e);
    }
    g_sa[j * NCHAN + chan] = a;
    g_sb[j * NCHAN + chan] = bb;
}

__global__ void __launch_bounds__(256) wkv_scan(const float* __restrict__ decay) {
    int chan = blockIdx.x * blockDim.x + threadIdx.x;  // 8192
    if (chan >= NCHAN) return;
    int c = chan & (C_ - 1);
    const float w = -__expf(decay[c]);
    const float dw = __expf((float)CHL * w);   // decay across one full chunk

    float a = 0.f, bb = 0.f;
    #pragma unroll
    for (int j = 0; j < NCH; ++j) {
        g_pa[j * NCHAN + chan] = a;
        g_pb[j * NCHAN + chan] = bb;
        a  = fmaf(a,  dw, g_sa[j * NCHAN + chan]);
        bb = fmaf(bb, dw, g_sb[j * NCHAN + chan]);
    }
}

// out: writes sigmoid(r)*y as HALF into g_ao (row stride 2048, K-offset 0)
__global__ void __launch_bounds__(256) wkv_out(const float* __restrict__ decay,
                                               const float* __restrict__ first,
                                               const float* __restrict__ ek,
                                               const float* __restrict__ v,
                                               const float* __restrict__ r,
                                               __half* __restrict__ out) {
    int gid = blockIdx.x * blockDim.x + threadIdx.x;
    int j    = gid >> 13;
    int chan = gid & (NCHAN - 1);
    int b = chan >> 10;
    int c = chan & (C_ - 1);
    const float ew = __expf(-__expf(decay[c]));
    const float eu = __expf(first[c]);
    size_t off  = ((size_t)b * T_ + (size_t)j * CHL) * C_ + c;
    size_t offo = ((size_t)b * T_ + (size_t)j * CHL) * 2048 + c;

    float a  = g_pa[j * NCHAN + chan];
    float bb = g_pb[j * NCHAN + chan];

    #pragma unroll 4
    for (int t = 0; t < CHL; ++t, off += C_, offo += 2048) {
        const float e  = ek[off];
        const float vt = v[off];
        const float x  = eu * e;
        const float y  = __fdividef(fmaf(x, vt, a), bb + x);
        out[offo] = __float2half_rn(y * r[off]);
        a  = fmaf(ew, a, e * vt);
        bb = fmaf(ew, bb, e);
    }
}

// ---------------------------------------------------------------------------
// fp16 tensor-core GEMM:  C[M,N] = A[M,K] * W[N,K]^T   (A, W half; fp32 acc)
// 128x128 CTA tile, BK=32 halfs, 256 threads (8 warps @ 64x32),
// 3-stage cp.async pipeline, 2 CTAs/SM, ldmatrix fragment loads.
// MODE: 0 = store f32, 1 = sigmoid f32, 2 = relu^2 -> half,
//       4 = aux1 + sigmoid(acc)*aux2 f32, 5 = exp f32
// ---------------------------------------------------------------------------
#define BM 128
#define BN 128
#define BK 32
#define BKPH 40
#define STG 3
#define STAGE_HALFS (128 * BKPH)
#define GEMM_SMEM (STG * STAGE_HALFS * 2 * 2)   // 61440 bytes

template <int MODE>
__global__ void __launch_bounds__(256, 2) gemm_tc(const __half* __restrict__ A,
                                                  const __half* __restrict__ W,
                                                  void* __restrict__ Cc,
                                                  const float* __restrict__ aux1,
                                                  const float* __restrict__ aux2,
                                                  int N, int K) {
    extern __shared__ __half smh[];
    __half* AsBase = smh;
    __half* BsBase = smh + STG * STAGE_HALFS;

    const int tid  = threadIdx.x;
    const int wid  = tid >> 5;
    const int lane = tid & 31;
    const int g    = lane >> 2;
    const int tig  = lane & 3;

    const int warp_m = wid >> 2;
    const int warp_n = wid & 3;

    const size_t brow = blockIdx.y;
    const size_t bcol = blockIdx.x;

    const int lrow = tid >> 1;
    const int lk   = (tid & 1) * 16;

    const __half* Ag = A + (brow * BM + lrow) * (size_t)K + lk;
    const __half* Wg = W + (bcol * BN + lrow) * (size_t)K + lk;

    const uint32_t smA = (uint32_t)__cvta_generic_to_shared(AsBase);
    const uint32_t smB = (uint32_t)__cvta_generic_to_shared(BsBase);
    const uint32_t aBase = smA +
        (((uint32_t)(warp_m * 64 + (lane & 15)) * BKPH + (uint32_t)(lane >> 4) * 8) << 1);
    const uint32_t bBase = smB +
        (((uint32_t)(warp_n * 32 + ((lane >> 4) << 3) + (lane & 7)) * BKPH +
          (uint32_t)((lane >> 3) & 1) * 8) << 1);

    float acc[4][4][4];
    #pragma unroll
    for (int i = 0; i < 4; ++i)
        #pragma unroll
        for (int j = 0; j < 4; ++j)
            #pragma unroll
            for (int r = 0; r < 4; ++r) acc[i][j][r] = 0.f;

    auto load_stage = [&](int s, int k0) {
        __half* a = AsBase + s * STAGE_HALFS + lrow * BKPH + lk;
        __half* b = BsBase + s * STAGE_HALFS + lrow * BKPH + lk;
        cp_async16(a,     Ag + k0);
        cp_async16(a + 8, Ag + k0 + 8);
        cp_async16(b,     Wg + k0);
        cp_async16(b + 8, Wg + k0 + 8);
    };

    load_stage(0, 0); CP_COMMIT();
    load_stage(1, BK); CP_COMMIT();

    const int nk = K / BK;
    for (int it = 0; it < nk; ++it) {
        const int cur = it % 3;
        if (it == nk - 1) { CP_WAIT0(); } else { CP_WAIT1(); }
        __syncthreads();

        const uint32_t soff = (uint32_t)cur * (STAGE_HALFS * 2);

        #pragma unroll
        for (int ks = 0; ks < 2; ++ks) {
            const uint32_t koff = (uint32_t)ks * 32;
            uint32_t af[4][4];
            uint32_t b0[4], b1[4];
            ldsm_x4(b0, bBase + soff + koff);
            ldsm_x4(b1, bBase + soff + koff + 16 * BKPH * 2);
            #pragma unroll
            for (int mt = 0; mt < 4; ++mt)
                ldsm_x4(af[mt], aBase + soff + koff + (uint32_t)mt * (16 * BKPH * 2));
            #pragma unroll
            for (int mt = 0; mt < 4; ++mt) {
                mma_f16(acc[mt][0], af[mt], b0);
                mma_f16(acc[mt][1], af[mt], b0 + 2);
                mma_f16(acc[mt][2], af[mt], b1);
                mma_f16(acc[mt][3], af[mt], b1 + 2);
            }
        }

        if (it + 2 < nk) {
            load_stage((it + 2) % 3, (it + 2) * BK);
            CP_COMMIT();
        }
    }

    // Epilogue
    #pragma unroll
    for (int mt = 0; mt < 4; ++mt) {
        const int r0 = (int)(brow * BM) + warp_m * 64 + mt * 16 + g;
        #pragma unroll
        for (int nt = 0; nt < 4; ++nt) {
            const int c0 = (int)(bcol * BN) + warp_n * 32 + nt * 8 + 2 * tig;
            #pragma unroll
            for (int half_i = 0; half_i < 2; ++half_i) {
                const int row = r0 + half_i * 8;
                const size_t off = (size_t)row * N + c0;
                float v0 = acc[mt][nt][half_i * 2 + 0];
                float v1 = acc[mt][nt][half_i * 2 + 1];
                if (MODE == 1) {
                    v0 = 1.f / (1.f + __expf(-v0));
                    v1 = 1.f / (1.f + __expf(-v1));
                } else if (MODE == 2) {
                    v0 = fmaxf(v0, 0.f); v0 = v0 * v0;
                    v1 = fmaxf(v1, 0.f); v1 = v1 * v1;
                } else if (MODE == 4) {
                    float2 a1 = *(const float2*)(aux1 + off);
                    float2 a2 = *(const float2*)(aux2 + off);
                    v0 = a1.x + (1.f / (1.f + __expf(-v0))) * a2.x;
                    v1 = a1.y + (1.f / (1.f + __expf(-v1))) * a2.y;
                } else if (MODE == 5) {
                    v0 = __expf(v0);
                    v1 = __expf(v1);
                }
                if (MODE == 2) {
                    __half2 hv = __floats2half2_rn(v0, v1);
                    *(__half2*)((__half*)Cc + off) = hv;
                } else {
                    float2 o; o.x = v0; o.y = v1;
                    *(float2*)((float*)Cc + off) = o;
                }
            }
        }
    }
}

// ---------------------------------------------------------------------------
// Launch
// ---------------------------------------------------------------------------
template <typename T>
static T* sym(const void* s) {
    void* p = nullptr;
    cudaGetSymbolAddress(&p, s);
    return (T*)p;
}

extern "C" void kernel_launch(void* const* d_in, const int* in_sizes, int n_in,
                              void* d_out, int out_size) {
    const float* x        = (const float*)d_in[0];
    const float* ln1_w    = (const float*)d_in[1];
    const float* ln1_b    = (const float*)d_in[2];
    const float* ln2_w    = (const float*)d_in[3];
    const float* ln2_b    = (const float*)d_in[4];
    const float* t_decay  = (const float*)d_in[5];
    const float* t_first  = (const float*)d_in[6];
    const float* mix_k    = (const float*)d_in[7];
    const float* mix_v    = (const float*)d_in[8];
    const float* mix_r    = (const float*)d_in[9];
    const float* Wk       = (const float*)d_in[10];
    const float* Wv       = (const float*)d_in[11];
    const float* Wr       = (const float*)d_in[12];
    const float* Wo       = (const float*)d_in[13];
    const float* fmix_k   = (const float*)d_in[14];
    const float* fmix_r   = (const float*)d_in[15];
    const float* fWk      = (const float*)d_in[16];   // [F, C]
    const float* fWr      = (const float*)d_in[17];   // [C, C]
    const float* fWv      = (const float*)d_in[18];   // [C, F]
    const float* shortW   = (const float*)d_in[19];
    float* out = (float*)d_out;

    float*  h    = sym<float>(g_h);
    __half* xk   = sym<__half>(g_xk);
    __half* xv   = sym<__half>(g_xv);
    __half* xr   = sym<__half>(g_xr);
    float*  ekb  = sym<float>(g_ek);
    float*  vbuf = sym<float>(g_v);
    float*  rbuf = sym<float>(g_r);
    __half* ao   = sym<__half>(g_ao);
    float*  x2   = sym<float>(g_x2);
    float*  gbuf = sym<float>(g_g);
    __half* gk   = sym<__half>(g_gk);
    __half* gr   = sym<__half>(g_gr);
    float*  kvb  = sym<float>(g_kv);
    __half* kkb  = sym<__half>(g_kk);
    __half* wkt  = sym<__half>(g_wkt);
    __half* wvt  = sym<__half>(g_wvt);
    __half* wrt  = sym<__half>(g_wrt);
    __half* wos  = sym<__half>(g_wos);
    __half* fwrt = sym<__half>(g_fwrt);
    __half* fwkt = sym<__half>(g_fwkt);
    __half* fwvt = sym<__half>(g_fwvt);

    cudaFuncSetAttribute(gemm_tc<0>, cudaFuncAttributeMaxDynamicSharedMemorySize, GEMM_SMEM);
    cudaFuncSetAttribute(gemm_tc<1>, cudaFuncAttributeMaxDynamicSharedMemorySize, GEMM_SMEM);
    cudaFuncSetAttribute(gemm_tc<2>, cudaFuncAttributeMaxDynamicSharedMemorySize, GEMM_SMEM);
    cudaFuncSetAttribute(gemm_tc<4>, cudaFuncAttributeMaxDynamicSharedMemorySize, GEMM_SMEM);
    cudaFuncSetAttribute(gemm_tc<5>, cudaFuncAttributeMaxDynamicSharedMemorySize, GEMM_SMEM);

    const dim3 blk(256);
    const dim3 grid_vec4((unsigned)((S_ / 4 + 255) / 256));
    const dim3 grid_gC(C_ / BN, M_ / BM);   // (8, 128)
    const dim3 grid_gF(F_ / BN, M_ / BM);   // (32, 128)

    const int nCC4 = (int)(CC_ / 4), nFC4 = (int)(FC_ / 4), nS4 = (int)(S_ / 4);
    // x -> half into g_ao K-offset 1024 (256 uint2)
    cvt_strided<<<(nS4 + 255) / 256, blk>>>(x, ao, nS4, 256);
    cvt_kernel<<<(nCC4 + 255) / 256, blk>>>(Wk, wkt, nCC4);
    cvt_kernel<<<(nCC4 + 255) / 256, blk>>>(Wv, wvt, nCC4);
    cvt_kernel<<<(nCC4 + 255) / 256, blk>>>(Wr, wrt, nCC4);
    cvt_strided<<<(nCC4 + 255) / 256, blk>>>(Wo, wos, nCC4, 0);
    cvt_strided<<<(nCC4 + 255) / 256, blk>>>(shortW, wos, nCC4, 256);
    cvt_kernel<<<(nCC4 + 255) / 256, blk>>>(fWr, fwrt, nCC4);
    cvt_kernel<<<(nFC4 + 255) / 256, blk>>>(fWk, fwkt, nFC4);
    cvt_kernel<<<(nFC4 + 255) / 256, blk>>>(fWv, fwvt, nFC4);

    // --- TimeMix path ---
    ln_kernel<<<M_, blk>>>(x, ln1_w, ln1_b, h);
    mix3_kernel<<<grid_vec4, blk>>>(h, mix_k, mix_v, mix_r, xk, xv, xr);
    gemm_tc<5><<<grid_gC, blk, GEMM_SMEM>>>(xk, wkt, ekb, nullptr, nullptr, C_, C_);   // exp(k)
    gemm_tc<0><<<grid_gC, blk, GEMM_SMEM>>>(xv, wvt, vbuf, nullptr, nullptr, C_, C_);
    gemm_tc<1><<<grid_gC, blk, GEMM_SMEM>>>(xr, wrt, rbuf, nullptr, nullptr, C_, C_);  // sigmoid(r)
    wkv_part<<<(NCHAN * NCH) / 256, blk>>>(t_decay, ekb, vbuf);
    wkv_scan<<<NCHAN / 256, blk>>>(t_decay);
    wkv_out<<<(NCHAN * NCH) / 256, blk>>>(t_decay, t_first, ekb, vbuf, rbuf, ao);
    // x2 = [rwkv | x] @ [Wo | shortW]^T   (K = 2048)
    gemm_tc<0><<<grid_gC, blk, GEMM_SMEM>>>(ao, wos, x2, nullptr, nullptr, C_, 2048);

    // --- ChannelMix path ---
    ln_kernel<<<M_, blk>>>(x2, ln2_w, ln2_b, gbuf);
    mix2_kernel<<<grid_vec4, blk>>>(gbuf, fmix_k, fmix_r, gk, gr);
    gemm_tc<2><<<grid_gF, blk, GEMM_SMEM>>>(gk, fwkt, kkb, nullptr, nullptr, F_, C_);
    gemm_tc<0><<<grid_gC, blk, GEMM_SMEM>>>(kkb, fwvt, kvb, nullptr, nullptr, C_, F_);
    gemm_tc<4><<<grid_gC, blk, GEMM_SMEM>>>(gr, fwrt, out, x2, kvb, C_, C_);
}

// round 10
// speedup vs baseline: 2.6963x; 1.0191x over previous
#include <cuda_runtime.h>
#include <cuda_fp16.h>
#include <math.h>
#include <stdint.h>

// Problem dims (fixed by the reference)
#define B_ 8
#define T_ 2048
#define C_ 1024
#define F_ 4096
#define M_ (B_ * T_)   // 16384 rows

constexpr size_t S_  = (size_t)M_ * C_;   // 16,777,216
constexpr size_t SF_ = (size_t)M_ * F_;   // 67,108,864
constexpr size_t CC_ = (size_t)C_ * C_;
constexpr size_t FC_ = (size_t)F_ * C_;

#define NCH 16            // WKV chunks
#define CHL (T_ / NCH)    // 128 steps per chunk
#define NCHAN (B_ * C_)   // 8192 channels

// ---------------------------------------------------------------------------
// Scratch (static device globals — allocation-free per harness rules)
// ---------------------------------------------------------------------------
__device__ __half g_xk[S_];
__device__ __half g_xv[S_];
__device__ __half g_xr[S_];
__device__ float  g_ek[S_];     // exp(k)  (from Wk GEMM epilogue)
__device__ float  g_v[S_];
__device__ float  g_r[S_];      // sigmoid(r)
__device__ __half g_ao[(size_t)M_ * 2048];  // [rwkv | x_half] along K
__device__ float  g_x2[S_];
__device__ __half g_gk[S_];
__device__ __half g_gr[S_];
__device__ float  g_kv[S_];
__device__ __half g_kk[SF_];
// half weights
__device__ __half g_wkt[CC_];
__device__ __half g_wvt[CC_];
__device__ __half g_wrt[CC_];
__device__ __half g_wos[2 * CC_];  // [Wo | shortW] along K
__device__ __half g_fwrt[CC_];
__device__ __half g_fwkt[FC_];
__device__ __half g_fwvt[FC_];
// WKV chunk-scan state (a, b per chunk)
__device__ float g_sa[NCHAN * NCH], g_sb[NCHAN * NCH];
__device__ float g_pa[NCHAN * NCH], g_pb[NCHAN * NCH];

// ---------------------------------------------------------------------------
// helpers
// ---------------------------------------------------------------------------
__device__ __forceinline__ void cp_async16(void* smem, const void* gmem) {
    uint32_t s = (uint32_t)__cvta_generic_to_shared(smem);
    asm volatile("cp.async.cg.shared.global [%0], [%1], 16;" :: "r"(s), "l"(gmem));
}
#define CP_COMMIT() asm volatile("cp.async.commit_group;")
#define CP_WAIT0()  asm volatile("cp.async.wait_group 0;")
#define CP_WAIT1()  asm volatile("cp.async.wait_group 1;")

__device__ __forceinline__ void mma_f16(float* d, const uint32_t* a, const uint32_t* b) {
    asm volatile(
        "mma.sync.aligned.m16n8k16.row.col.f32.f16.f16.f32 "
        "{%0,%1,%2,%3}, {%4,%5,%6,%7}, {%8,%9}, {%0,%1,%2,%3};"
        : "+f"(d[0]), "+f"(d[1]), "+f"(d[2]), "+f"(d[3])
        : "r"(a[0]), "r"(a[1]), "r"(a[2]), "r"(a[3]),
          "r"(b[0]), "r"(b[1]));
}

__device__ __forceinline__ void ldsm_x4(uint32_t* r, uint32_t addr) {
    asm volatile("ldmatrix.sync.aligned.m8n8.x4.shared.b16 {%0,%1,%2,%3}, [%4];"
        : "=r"(r[0]), "=r"(r[1]), "=r"(r[2]), "=r"(r[3]) : "r"(addr));
}

// ---------------------------------------------------------------------------
// float -> half copy-convert (plain, contiguous)
// ---------------------------------------------------------------------------
__global__ void __launch_bounds__(256) cvt_kernel(const float* __restrict__ src,
                                                  __half* __restrict__ dst,
                                                  int n4) {
    int i = blockIdx.x * blockDim.x + threadIdx.x;
    if (i >= n4) return;
    float4 v = ((const float4*)src)[i];
    __half2 h0 = __floats2half2_rn(v.x, v.y);
    __half2 h1 = __floats2half2_rn(v.z, v.w);
    uint2 o;
    o.x = *(uint32_t*)&h0;
    o.y = *(uint32_t*)&h1;
    ((uint2*)dst)[i] = o;
}

// float -> half into a row-strided buffer (row stride 2048 halfs)
__global__ void __launch_bounds__(256) cvt_strided(const float* __restrict__ src,
                                                   __half* __restrict__ dst,
                                                   int n4, int off_u2) {
    int i4 = blockIdx.x * blockDim.x + threadIdx.x;
    if (i4 >= n4) return;
    int row = i4 >> 8;
    int col = i4 & 255;
    float4 v = ((const float4*)src)[i4];
    __half2 h0 = __floats2half2_rn(v.x, v.y);
    __half2 h1 = __floats2half2_rn(v.z, v.w);
    uint2 o;
    o.x = *(uint32_t*)&h0;
    o.y = *(uint32_t*)&h1;
    ((uint2*)dst)[(size_t)row * 512 + off_u2 + col] = o;
}

// ---------------------------------------------------------------------------
// Fused LayerNorm + time-shift-mix.
// One block owns ROWS_PB=32 consecutive t-rows of one batch. It computes the
// LN of each row sequentially (each thread holds 4 channels), keeping the
// previous row's normalized value in registers; the block-start boundary row
// is recomputed. NOUT=3 -> (xk,xv,xr); NOUT=2 -> (xk,xr).
// ---------------------------------------------------------------------------
#define ROWS_PB 32

template <int NOUT>
__global__ void __launch_bounds__(256) ln_mix_kernel(
        const float* __restrict__ x,
        const float* __restrict__ w, const float* __restrict__ b,
        const float* __restrict__ m0, const float* __restrict__ m1,
        const float* __restrict__ m2,
        __half* __restrict__ o0, __half* __restrict__ o1,
        __half* __restrict__ o2) {
    __shared__ float sm_s[8], sm_ss[8];
    const int tid = threadIdx.x;
    const int wid = tid >> 5, lid = tid & 31;
    const size_t row0 = (size_t)blockIdx.x * ROWS_PB;
    const bool at_t0 = ((row0 & (T_ - 1)) == 0);

    const float4 wv = ((const float4*)w)[tid];
    const float4 bv = ((const float4*)b)[tid];
    const float4 mk0 = ((const float4*)m0)[tid];
    const float4 mk1 = ((const float4*)m1)[tid];
    const float4 mk2 = (NOUT == 3) ? ((const float4*)m2)[tid]
                                   : make_float4(0.f, 0.f, 0.f, 0.f);

    auto ln_row = [&](size_t row) -> float4 {
        float4 xv4 = ((const float4*)(x + row * C_))[tid];
        float s  = xv4.x + xv4.y + xv4.z + xv4.w;
        float ss = xv4.x * xv4.x + xv4.y * xv4.y + xv4.z * xv4.z + xv4.w * xv4.w;
        #pragma unroll
        for (int o = 16; o > 0; o >>= 1) {
            s  += __shfl_down_sync(0xffffffffu, s,  o);
            ss += __shfl_down_sync(0xffffffffu, ss, o);
        }
        __syncthreads();   // protect smem from previous iteration
        if (lid == 0) { sm_s[wid] = s; sm_ss[wid] = ss; }
        __syncthreads();
        float ts = 0.f, tss = 0.f;
        #pragma unroll
        for (int q = 0; q < 8; ++q) { ts += sm_s[q]; tss += sm_ss[q]; }
        const float mean = ts * (1.0f / C_);
        const float var  = tss * (1.0f / C_) - mean * mean;
        const float rstd = rsqrtf(var + 1e-5f);
        float4 r;
        r.x = (xv4.x - mean) * rstd * wv.x + bv.x;
        r.y = (xv4.y - mean) * rstd * wv.y + bv.y;
        r.z = (xv4.z - mean) * rstd * wv.z + bv.z;
        r.w = (xv4.w - mean) * rstd * wv.w + bv.w;
        return r;
    };

    float4 prev = make_float4(0.f, 0.f, 0.f, 0.f);
    if (!at_t0) prev = ln_row(row0 - 1);

    for (int i = 0; i < ROWS_PB; ++i) {
        const size_t row = row0 + i;
        float4 cur = ln_row(row);
        const size_t o4 = row * (C_ / 4) + tid;

        {
            float a0 = cur.x * mk0.x + prev.x * (1.f - mk0.x);
            float a1 = cur.y * mk0.y + prev.y * (1.f - mk0.y);
            float a2 = cur.z * mk0.z + prev.z * (1.f - mk0.z);
            float a3 = cur.w * mk0.w + prev.w * (1.f - mk0.w);
            __half2 p0 = __floats2half2_rn(a0, a1);
            __half2 p1 = __floats2half2_rn(a2, a3);
            uint2 o; o.x = *(uint32_t*)&p0; o.y = *(uint32_t*)&p1;
            ((uint2*)o0)[o4] = o;
        }
        {
            float a0 = cur.x * mk1.x + prev.x * (1.f - mk1.x);
            float a1 = cur.y * mk1.y + prev.y * (1.f - mk1.y);
            float a2 = cur.z * mk1.z + prev.z * (1.f - mk1.z);
            float a3 = cur.w * mk1.w + prev.w * (1.f - mk1.w);
            __half2 p0 = __floats2half2_rn(a0, a1);
            __half2 p1 = __floats2half2_rn(a2, a3);
            uint2 o; o.x = *(uint32_t*)&p0; o.y = *(uint32_t*)&p1;
            ((uint2*)o1)[o4] = o;
        }
        if (NOUT == 3) {
            float a0 = cur.x * mk2.x + prev.x * (1.f - mk2.x);
            float a1 = cur.y * mk2.y + prev.y * (1.f - mk2.y);
            float a2 = cur.z * mk2.z + prev.z * (1.f - mk2.z);
            float a3 = cur.w * mk2.w + prev.w * (1.f - mk2.w);
            __half2 p0 = __floats2half2_rn(a0, a1);
            __half2 p1 = __floats2half2_rn(a2, a3);
            uint2 o; o.x = *(uint32_t*)&p0; o.y = *(uint32_t*)&p1;
            ((uint2*)o2)[o4] = o;
        }
        prev = cur;
    }
}

// ---------------------------------------------------------------------------
// WKV chunk-parallel scan, UNNORMALIZED form (exp(k) precomputed in GEMM)
// ---------------------------------------------------------------------------
__global__ void __launch_bounds__(256) wkv_part(const float* __restrict__ decay,
                                                const float* __restrict__ ek,
                                                const float* __restrict__ v) {
    int gid = blockIdx.x * blockDim.x + threadIdx.x;  // 131072
    int j    = gid >> 13;
    int chan = gid & (NCHAN - 1);
    int b = chan >> 10;
    int c = chan & (C_ - 1);
    const float ew = __expf(-__expf(decay[c]));
    size_t off = ((size_t)b * T_ + (size_t)j * CHL) * C_ + c;

    float a = 0.f, bb = 0.f;
    #pragma unroll 4
    for (int t = 0; t < CHL; ++t, off += C_) {
        const float e = ek[off];
        const float vt = v[off];
        a  = fmaf(ew, a, e * vt);
        bb = fmaf(ew, bb, e);
    }
    g_sa[j * NCHAN + chan] = a;
    g_sb[j * NCHAN + chan] = bb;
}

__global__ void __launch_bounds__(256) wkv_scan(const float* __restrict__ decay) {
    int chan = blockIdx.x * blockDim.x + threadIdx.x;  // 8192
    if (chan >= NCHAN) return;
    int c = chan & (C_ - 1);
    const float w = -__expf(decay[c]);
    const float dw = __expf((float)CHL * w);

    float a = 0.f, bb = 0.f;
    #pragma unroll
    for (int j = 0; j < NCH; ++j) {
        g_pa[j * NCHAN + chan] = a;
        g_pb[j * NCHAN + chan] = bb;
        a  = fmaf(a,  dw, g_sa[j * NCHAN + chan]);
        bb = fmaf(bb, dw, g_sb[j * NCHAN + chan]);
    }
}

__global__ void __launch_bounds__(256) wkv_out(const float* __restrict__ decay,
                                               const float* __restrict__ first,
                                               const float* __restrict__ ek,
                                               const float* __restrict__ v,
                                               const float* __restrict__ r,
                                               __half* __restrict__ out) {
    int gid = blockIdx.x * blockDim.x + threadIdx.x;
    int j    = gid >> 13;
    int chan = gid & (NCHAN - 1);
    int b = chan >> 10;
    int c = chan & (C_ - 1);
    const float ew = __expf(-__expf(decay[c]));
    const float eu = __expf(first[c]);
    size_t off  = ((size_t)b * T_ + (size_t)j * CHL) * C_ + c;
    size_t offo = ((size_t)b * T_ + (size_t)j * CHL) * 2048 + c;

    float a  = g_pa[j * NCHAN + chan];
    float bb = g_pb[j * NCHAN + chan];

    #pragma unroll 4
    for (int t = 0; t < CHL; ++t, off += C_, offo += 2048) {
        const float e  = ek[off];
        const float vt = v[off];
        const float x  = eu * e;
        const float y  = __fdividef(fmaf(x, vt, a), bb + x);
        out[offo] = __float2half_rn(y * r[off]);
        a  = fmaf(ew, a, e * vt);
        bb = fmaf(ew, bb, e);
    }
}

// ---------------------------------------------------------------------------
// fp16 tensor-core GEMM core (shared by single + batched kernels)
// 128x128 CTA tile, BK=32 halfs, 256 threads (8 warps @ 64x32),
// 3-stage cp.async pipeline, 2 CTAs/SM, ldmatrix fragment loads.
// ---------------------------------------------------------------------------
#define BM 128
#define BN 128
#define BK 32
#define BKPH 40
#define STG 3
#define STAGE_HALFS (128 * BKPH)
#define GEMM_SMEM (STG * STAGE_HALFS * 2 * 2)   // 61440 bytes

struct GemmCtx {
    uint32_t aBase, bBase;
    int lrow, lk;
    const __half* Ag;
    const __half* Wg;
    __half* AsBase;
    __half* BsBase;
};

__device__ __forceinline__ void gemm_main(GemmCtx& cx, float acc[4][4][4], int K) {
    auto load_stage = [&](int s, int k0) {
        __half* a = cx.AsBase + s * STAGE_HALFS + cx.lrow * BKPH + cx.lk;
        __half* b = cx.BsBase + s * STAGE_HALFS + cx.lrow * BKPH + cx.lk;
        cp_async16(a,     cx.Ag + k0);
        cp_async16(a + 8, cx.Ag + k0 + 8);
        cp_async16(b,     cx.Wg + k0);
        cp_async16(b + 8, cx.Wg + k0 + 8);
    };

    load_stage(0, 0); CP_COMMIT();
    load_stage(1, BK); CP_COMMIT();

    const int nk = K / BK;
    for (int it = 0; it < nk; ++it) {
        const int cur = it % 3;
        if (it == nk - 1) { CP_WAIT0(); } else { CP_WAIT1(); }
        __syncthreads();

        const uint32_t soff = (uint32_t)cur * (STAGE_HALFS * 2);

        #pragma unroll
        for (int ks = 0; ks < 2; ++ks) {
            const uint32_t koff = (uint32_t)ks * 32;
            uint32_t af[4][4];
            uint32_t b0[4], b1[4];
            ldsm_x4(b0, cx.bBase + soff + koff);
            ldsm_x4(b1, cx.bBase + soff + koff + 16 * BKPH * 2);
            #pragma unroll
            for (int mt = 0; mt < 4; ++mt)
                ldsm_x4(af[mt], cx.aBase + soff + koff + (uint32_t)mt * (16 * BKPH * 2));
            #pragma unroll
            for (int mt = 0; mt < 4; ++mt) {
                mma_f16(acc[mt][0], af[mt], b0);
                mma_f16(acc[mt][1], af[mt], b0 + 2);
                mma_f16(acc[mt][2], af[mt], b1);
                mma_f16(acc[mt][3], af[mt], b1 + 2);
            }
        }

        if (it + 2 < nk) {
            load_stage((it + 2) % 3, (it + 2) * BK);
            CP_COMMIT();
        }
    }
}

__device__ __forceinline__ void gemm_setup(GemmCtx& cx, const __half* A,
                                           const __half* W, int K,
                                           __half* smh) {
    const int tid  = threadIdx.x;
    const int wid  = tid >> 5;
    const int lane = tid & 31;
    cx.AsBase = smh;
    cx.BsBase = smh + STG * STAGE_HALFS;
    cx.lrow = tid >> 1;
    cx.lk   = (tid & 1) * 16;
    cx.Ag = A + ((size_t)blockIdx.y * BM + cx.lrow) * (size_t)K + cx.lk;
    cx.Wg = W + ((size_t)blockIdx.x * BN + cx.lrow) * (size_t)K + cx.lk;
    const int warp_m = wid >> 2;
    const int warp_n = wid & 3;
    const uint32_t smA = (uint32_t)__cvta_generic_to_shared(cx.AsBase);
    const uint32_t smB = (uint32_t)__cvta_generic_to_shared(cx.BsBase);
    cx.aBase = smA +
        (((uint32_t)(warp_m * 64 + (lane & 15)) * BKPH + (uint32_t)(lane >> 4) * 8) << 1);
    cx.bBase = smB +
        (((uint32_t)(warp_n * 32 + ((lane >> 4) << 3) + (lane & 7)) * BKPH +
          (uint32_t)((lane >> 3) & 1) * 8) << 1);
}

// Per-element epilogue position helper
#define EPI_LOOP(BODY)                                                         \
    const int tid  = threadIdx.x;                                              \
    const int wid  = tid >> 5;                                                 \
    const int lane = tid & 31;                                                 \
    const int g    = lane >> 2;                                                \
    const int tig  = lane & 3;                                                 \
    const int warp_m = wid >> 2;                                               \
    const int warp_n = wid & 3;                                                \
    _Pragma("unroll")                                                          \
    for (int mt = 0; mt < 4; ++mt) {                                           \
        const int r0 = (int)(blockIdx.y * BM) + warp_m * 64 + mt * 16 + g;     \
        _Pragma("unroll")                                                      \
        for (int nt = 0; nt < 4; ++nt) {                                       \
            const int c0 = (int)(blockIdx.x * BN) + warp_n * 32 + nt * 8 + 2 * tig; \
            _Pragma("unroll")                                                  \
            for (int hi = 0; hi < 2; ++hi) {                                   \
                const int row = r0 + hi * 8;                                   \
                const size_t off = (size_t)row * N + c0;                       \
                float v0 = acc[mt][nt][hi * 2 + 0];                            \
                float v1 = acc[mt][nt][hi * 2 + 1];                            \
                BODY                                                           \
            }                                                                  \
        }                                                                      \
    }

// Single GEMM, MODE: 0 store f32, 2 relu^2->half, 4 aux1+sigmoid(acc)*aux2
template <int MODE>
__global__ void __launch_bounds__(256, 2) gemm_tc(const __half* __restrict__ A,
                                                  const __half* __restrict__ W,
                                                  void* __restrict__ Cc,
                                                  const float* __restrict__ aux1,
                                                  const float* __restrict__ aux2,
                                                  int N, int K) {
    extern __shared__ __half smh[];
    GemmCtx cx;
    gemm_setup(cx, A, W, K, smh);
    float acc[4][4][4];
    #pragma unroll
    for (int i = 0; i < 4; ++i)
        #pragma unroll
        for (int j = 0; j < 4; ++j)
            #pragma unroll
            for (int r = 0; r < 4; ++r) acc[i][j][r] = 0.f;
    gemm_main(cx, acc, K);

    EPI_LOOP({
        if (MODE == 2) {
            v0 = fmaxf(v0, 0.f); v0 = v0 * v0;
            v1 = fmaxf(v1, 0.f); v1 = v1 * v1;
            __half2 hv = __floats2half2_rn(v0, v1);
            *(__half2*)((__half*)Cc + off) = hv;
        } else if (MODE == 4) {
            float2 a1 = *(const float2*)(aux1 + off);
            float2 a2 = *(const float2*)(aux2 + off);
            v0 = a1.x + (1.f / (1.f + __expf(-v0))) * a2.x;
            v1 = a1.y + (1.f / (1.f + __expf(-v1))) * a2.y;
            float2 o; o.x = v0; o.y = v1;
            *(float2*)((float*)Cc + off) = o;
        } else {
            float2 o; o.x = v0; o.y = v1;
            *(float2*)((float*)Cc + off) = o;
        }
    })
}

// Batched TimeMix triple GEMM: z=0 exp(k), z=1 v, z=2 sigmoid(r)
__global__ void __launch_bounds__(256, 2) gemm_tc3(
        const __half* __restrict__ A0, const __half* __restrict__ A1,
        const __half* __restrict__ A2,
        const __half* __restrict__ W0, const __half* __restrict__ W1,
        const __half* __restrict__ W2,
        float* __restrict__ C0, float* __restrict__ C1,
        float* __restrict__ C2, int N, int K) {
    extern __shared__ __half smh[];
    const int z = blockIdx.z;
    const __half* A = (z == 0) ? A0 : (z == 1) ? A1 : A2;
    const __half* W = (z == 0) ? W0 : (z == 1) ? W1 : W2;
    float* Cc       = (z == 0) ? C0 : (z == 1) ? C1 : C2;

    GemmCtx cx;
    gemm_setup(cx, A, W, K, smh);
    float acc[4][4][4];
    #pragma unroll
    for (int i = 0; i < 4; ++i)
        #pragma unroll
        for (int j = 0; j < 4; ++j)
            #pragma unroll
            for (int r = 0; r < 4; ++r) acc[i][j][r] = 0.f;
    gemm_main(cx, acc, K);

    EPI_LOOP({
        if (z == 0) {
            v0 = __expf(v0); v1 = __expf(v1);
        } else if (z == 2) {
            v0 = 1.f / (1.f + __expf(-v0));
            v1 = 1.f / (1.f + __expf(-v1));
        }
        float2 o; o.x = v0; o.y = v1;
        *(float2*)(Cc + off) = o;
    })
}

// ---------------------------------------------------------------------------
// Launch
// ---------------------------------------------------------------------------
template <typename T>
static T* sym(const void* s) {
    void* p = nullptr;
    cudaGetSymbolAddress(&p, s);
    return (T*)p;
}

extern "C" void kernel_launch(void* const* d_in, const int* in_sizes, int n_in,
                              void* d_out, int out_size) {
    const float* x        = (const float*)d_in[0];
    const float* ln1_w    = (const float*)d_in[1];
    const float* ln1_b    = (const float*)d_in[2];
    const float* ln2_w    = (const float*)d_in[3];
    const float* ln2_b    = (const float*)d_in[4];
    const float* t_decay  = (const float*)d_in[5];
    const float* t_first  = (const float*)d_in[6];
    const float* mix_k    = (const float*)d_in[7];
    const float* mix_v    = (const float*)d_in[8];
    const float* mix_r    = (const float*)d_in[9];
    const float* Wk       = (const float*)d_in[10];
    const float* Wv       = (const float*)d_in[11];
    const float* Wr       = (const float*)d_in[12];
    const float* Wo       = (const float*)d_in[13];
    const float* fmix_k   = (const float*)d_in[14];
    const float* fmix_r   = (const float*)d_in[15];
    const float* fWk      = (const float*)d_in[16];   // [F, C]
    const float* fWr      = (const float*)d_in[17];   // [C, C]
    const float* fWv      = (const float*)d_in[18];   // [C, F]
    const float* shortW   = (const float*)d_in[19];
    float* out = (float*)d_out;

    __half* xk   = sym<__half>(g_xk);
    __half* xv   = sym<__half>(g_xv);
    __half* xr   = sym<__half>(g_xr);
    float*  ekb  = sym<float>(g_ek);
    float*  vbuf = sym<float>(g_v);
    float*  rbuf = sym<float>(g_r);
    __half* ao   = sym<__half>(g_ao);
    float*  x2   = sym<float>(g_x2);
    __half* gk   = sym<__half>(g_gk);
    __half* gr   = sym<__half>(g_gr);
    float*  kvb  = sym<float>(g_kv);
    __half* kkb  = sym<__half>(g_kk);
    __half* wkt  = sym<__half>(g_wkt);
    __half* wvt  = sym<__half>(g_wvt);
    __half* wrt  = sym<__half>(g_wrt);
    __half* wos  = sym<__half>(g_wos);
    __half* fwrt = sym<__half>(g_fwrt);
    __half* fwkt = sym<__half>(g_fwkt);
    __half* fwvt = sym<__half>(g_fwvt);

    cudaFuncSetAttribute(gemm_tc<0>, cudaFuncAttributeMaxDynamicSharedMemorySize, GEMM_SMEM);
    cudaFuncSetAttribute(gemm_tc<2>, cudaFuncAttributeMaxDynamicSharedMemorySize, GEMM_SMEM);
    cudaFuncSetAttribute(gemm_tc<4>, cudaFuncAttributeMaxDynamicSharedMemorySize, GEMM_SMEM);
    cudaFuncSetAttribute(gemm_tc3, cudaFuncAttributeMaxDynamicSharedMemorySize, GEMM_SMEM);

    const dim3 blk(256);
    const dim3 grid_gC(C_ / BN, M_ / BM);        // (8, 128)
    const dim3 grid_gC3(C_ / BN, M_ / BM, 3);    // batched triple
    const dim3 grid_gF(F_ / BN, M_ / BM);        // (32, 128)
    const dim3 grid_lnmix(M_ / ROWS_PB);         // 512

    const int nCC4 = (int)(CC_ / 4), nFC4 = (int)(FC_ / 4), nS4 = (int)(S_ / 4);
    // x -> half into g_ao K-offset 1024 (256 uint2)
    cvt_strided<<<(nS4 + 255) / 256, blk>>>(x, ao, nS4, 256);
    cvt_kernel<<<(nCC4 + 255) / 256, blk>>>(Wk, wkt, nCC4);
    cvt_kernel<<<(nCC4 + 255) / 256, blk>>>(Wv, wvt, nCC4);
    cvt_kernel<<<(nCC4 + 255) / 256, blk>>>(Wr, wrt, nCC4);
    cvt_strided<<<(nCC4 + 255) / 256, blk>>>(Wo, wos, nCC4, 0);
    cvt_strided<<<(nCC4 + 255) / 256, blk>>>(shortW, wos, nCC4, 256);
    cvt_kernel<<<(nCC4 + 255) / 256, blk>>>(fWr, fwrt, nCC4);
    cvt_kernel<<<(nFC4 + 255) / 256, blk>>>(fWk, fwkt, nFC4);
    cvt_kernel<<<(nFC4 + 255) / 256, blk>>>(fWv, fwvt, nFC4);

    // --- TimeMix path ---
    ln_mix_kernel<3><<<grid_lnmix, blk>>>(x, ln1_w, ln1_b,
                                          mix_k, mix_v, mix_r, xk, xv, xr);
    gemm_tc3<<<grid_gC3, blk, GEMM_SMEM>>>(xk, xv, xr, wkt, wvt, wrt,
                                           ekb, vbuf, rbuf, C_, C_);
    wkv_part<<<(NCHAN * NCH) / 256, blk>>>(t_decay, ekb, vbuf);
    wkv_scan<<<NCHAN / 256, blk>>>(t_decay);
    wkv_out<<<(NCHAN * NCH) / 256, blk>>>(t_decay, t_first, ekb, vbuf, rbuf, ao);
    // x2 = [rwkv | x] @ [Wo | shortW]^T   (K = 2048)
    gemm_tc<0><<<grid_gC, blk, GEMM_SMEM>>>(ao, wos, x2, nullptr, nullptr, C_, 2048);

    // --- ChannelMix path ---
    ln_mix_kernel<2><<<grid_lnmix, blk>>>(x2, ln2_w, ln2_b,
                                          fmix_k, fmix_r, nullptr, gk, gr, nullptr);
    gemm_tc<2><<<grid_gF, blk, GEMM_SMEM>>>(gk, fwkt, kkb, nullptr, nullptr, F_, C_);
    gemm_tc<0><<<grid_gC, blk, GEMM_SMEM>>>(kkb, fwvt, kvb, nullptr, nullptr, C_, F_);
    gemm_tc<4><<<grid_gC, blk, GEMM_SMEM>>>(gr, fwrt, out, x2, kvb, C_, C_);
}